// round 8
// baseline (speedup 1.0000x reference)
#include <cuda_runtime.h>
#include <cuda_bf16.h>
#include <cstdint>

#define HDIM 2048
#define MDIM 1408
#define NEXP 8
#define NTOK 1024

// ---------------- device scratch ----------------
__device__ __nv_bfloat16 g_xhi[NTOK * HDIM];
__device__ __nv_bfloat16 g_xlo[NTOK * HDIM];
__device__ __nv_bfloat16 g_ahi[(NEXP + 1) * NTOK * MDIM];
__device__ __nv_bfloat16 g_alo[(NEXP + 1) * NTOK * MDIM];
// weight bf16 hi/lo planes; slot NEXP = shared expert
__device__ __nv_bfloat16 g_wghi[(NEXP + 1) * MDIM * HDIM];
__device__ __nv_bfloat16 g_wglo[(NEXP + 1) * MDIM * HDIM];
__device__ __nv_bfloat16 g_wuhi[(NEXP + 1) * MDIM * HDIM];
__device__ __nv_bfloat16 g_wulo[(NEXP + 1) * MDIM * HDIM];
__device__ __nv_bfloat16 g_wdhi[(NEXP + 1) * HDIM * MDIM];
__device__ __nv_bfloat16 g_wdlo[(NEXP + 1) * HDIM * MDIM];
__device__ int   g_tok[NEXP * NTOK];
__device__ float g_wt[NEXP * NTOK];
__device__ int   g_cnt[NEXP];
__device__ float g_pisum[NEXP];

// ---------------- helpers ----------------
__device__ __forceinline__ uint32_t smem_u32(const void* p) {
    uint32_t a;
    asm("{ .reg .u64 t; cvta.to.shared.u64 t, %1; cvt.u32.u64 %0, t; }" : "=r"(a) : "l"(p));
    return a;
}
__device__ __forceinline__ void cp16(uint32_t dst, const void* src) {
    asm volatile("cp.async.cg.shared.global [%0], [%1], 16;" :: "r"(dst), "l"(src));
}
#define CP_COMMIT() asm volatile("cp.async.commit_group;" ::: "memory")
#define CP_WAIT1()  asm volatile("cp.async.wait_group 1;" ::: "memory")

#define LDSM4(r, addr)                                                                       \
    asm volatile("ldmatrix.sync.aligned.m8n8.x4.shared.b16 {%0,%1,%2,%3}, [%4];"             \
                 : "=r"((r)[0]), "=r"((r)[1]), "=r"((r)[2]), "=r"((r)[3]) : "r"(addr))
#define LDSM2(r, addr)                                                                       \
    asm volatile("ldmatrix.sync.aligned.m8n8.x2.shared.b16 {%0,%1}, [%2];"                   \
                 : "=r"((r)[0]), "=r"((r)[1]) : "r"(addr))
#define MMA(c, a, b)                                                                         \
    asm volatile("mma.sync.aligned.m16n8k16.row.col.f32.bf16.bf16.f32 "                      \
                 "{%0,%1,%2,%3},{%4,%5,%6,%7},{%8,%9},{%0,%1,%2,%3};"                        \
                 : "+f"((c)[0]), "+f"((c)[1]), "+f"((c)[2]), "+f"((c)[3])                    \
                 : "r"((a)[0]), "r"((a)[1]), "r"((a)[2]), "r"((a)[3]), "r"((b)[0]), "r"((b)[1]))

__device__ __forceinline__ void split2(float a, float b, uint32_t& hi, uint32_t& lo) {
    __nv_bfloat16 ha = __float2bfloat16(a), hb = __float2bfloat16(b);
    float ra = a - __bfloat162float(ha), rb = b - __bfloat162float(hb);
    __nv_bfloat16 la = __float2bfloat16(ra), lb = __float2bfloat16(rb);
    __nv_bfloat162 hp; hp.x = ha; hp.y = hb;
    __nv_bfloat162 lp; lp.x = la; lp.y = lb;
    hi = *reinterpret_cast<uint32_t*>(&hp);
    lo = *reinterpret_cast<uint32_t*>(&lp);
}

// 64B-row XOR swizzle: XOR 16B-segment index (bits 4:5) with row bits (7:8)
#define SWZ64(o) ((o) ^ (((o) >> 3) & 0x30))

// ---------------- init / conversions ----------------
__global__ void zero_kernel(float* __restrict__ y) {
    int i = blockIdx.x * blockDim.x + threadIdx.x;
    if (i < NTOK * HDIM) y[i] = 0.f;
    if (i < NEXP) { g_cnt[i] = 0; g_pisum[i] = 0.f; }
}

__global__ void xconv_kernel(const float* __restrict__ x) {
    int i = blockIdx.x * blockDim.x + threadIdx.x;
    if (i < NTOK * HDIM) {
        float v = x[i];
        __nv_bfloat16 h = __float2bfloat16(v);
        __nv_bfloat16 l = __float2bfloat16(v - __bfloat162float(h));
        g_xhi[i] = h; g_xlo[i] = l;
    }
}

// fp32 -> bf16 hi/lo planes; destination selected device-side
__global__ __launch_bounds__(256)
void wconv_kernel(const float4* __restrict__ src, int which, size_t dstOff, int n4) {
    int i = blockIdx.x * blockDim.x + threadIdx.x;
    if (i >= n4) return;
    __nv_bfloat16 *hb, *lb;
    if (which == 0)      { hb = g_wghi; lb = g_wglo; }
    else if (which == 1) { hb = g_wuhi; lb = g_wulo; }
    else                 { hb = g_wdhi; lb = g_wdlo; }
    uint2* hp = (uint2*)(hb + dstOff);
    uint2* lp = (uint2*)(lb + dstOff);
    float4 v = src[i];
    uint2 h, l;
    split2(v.x, v.y, h.x, l.x);
    split2(v.z, v.w, h.y, l.y);
    hp[i] = h; lp[i] = l;
}

// ---------------- gate ----------------
__global__ __launch_bounds__(256)
void gate_kernel(const float* __restrict__ x, const float* __restrict__ gw) {
    const int t = blockIdx.x;
    const float* xr = x + (size_t)t * HDIM;
    float acc[NEXP];
#pragma unroll
    for (int e = 0; e < NEXP; e++) acc[e] = 0.f;
    for (int h = threadIdx.x; h < HDIM; h += 256) {
        float xv = xr[h];
#pragma unroll
        for (int e = 0; e < NEXP; e++) acc[e] = fmaf(xv, gw[e * HDIM + h], acc[e]);
    }
#pragma unroll
    for (int e = 0; e < NEXP; e++)
        for (int o = 16; o > 0; o >>= 1) acc[e] += __shfl_down_sync(0xffffffffu, acc[e], o);

    __shared__ float red[8][NEXP];
    int warp = threadIdx.x >> 5, lane = threadIdx.x & 31;
    if (lane == 0) {
#pragma unroll
        for (int e = 0; e < NEXP; e++) red[warp][e] = acc[e];
    }
    __syncthreads();
    if (threadIdx.x == 0) {
        float lg[NEXP];
#pragma unroll
        for (int e = 0; e < NEXP; e++) {
            float s = 0.f;
            for (int w = 0; w < 8; w++) s += red[w][e];
            lg[e] = s;
        }
        float mx = lg[0];
#pragma unroll
        for (int e = 1; e < NEXP; e++) mx = fmaxf(mx, lg[e]);
        float p[NEXP]; float den = 0.f;
#pragma unroll
        for (int e = 0; e < NEXP; e++) { p[e] = __expf(lg[e] - mx); den += p[e]; }
#pragma unroll
        for (int e = 0; e < NEXP; e++) p[e] /= den;
#pragma unroll
        for (int e = 0; e < NEXP; e++) atomicAdd(&g_pisum[e], p[e]);
        int i1 = 0;
#pragma unroll
        for (int e = 1; e < NEXP; e++) if (p[e] > p[i1]) i1 = e;
        int i2 = -1;
#pragma unroll
        for (int e = 0; e < NEXP; e++) {
            if (e == i1) continue;
            if (i2 < 0 || p[e] > p[i2]) i2 = e;
        }
        float w1 = p[i1], w2 = p[i2];
        float s2 = w1 + w2 + 1e-20f;
        w1 /= s2; w2 /= s2;
        int pos1 = atomicAdd(&g_cnt[i1], 1);
        g_tok[i1 * NTOK + pos1] = t; g_wt[i1 * NTOK + pos1] = w1;
        int pos2 = atomicAdd(&g_cnt[i2], 1);
        g_tok[i2 * NTOK + pos2] = t; g_wt[i2 * NTOK + pos2] = w2;
    }
}

// =======================================================================
// gateup: act = silu(X Wg^T) * (X Wu^T)  tile 128x64, K chunk 32, 3-stage
// swizzled 64B rows; grid z: 0..7 routed experts, 8 = shared expert
// =======================================================================
#define GU_STG  32768
#define GU_AHI  0
#define GU_ALO  8192
#define GU_BGH  16384   // BGL +4096, BUH +8192, BUL +12288
#define GU_TOK  (3 * GU_STG)
#define GU_SM   (GU_TOK + 512)

__global__ __launch_bounds__(256, 2)
void gateup_mma() {
    extern __shared__ __align__(128) char sm[];
    const int z = blockIdx.z;
    const bool SH = (z == NEXP);
    const int nrows = SH ? NTOK : g_cnt[z];
    const int row0 = blockIdx.x * 128;
    if (row0 >= nrows) return;
    const int n0 = blockIdx.y * 64;

    const int tid = threadIdx.x, wid = tid >> 5, lane = tid & 31;
    int* toks = (int*)(sm + GU_TOK);
    if (tid < 128) {
        int r = row0 + tid;
        toks[tid] = (r < nrows) ? (SH ? r : g_tok[z * NTOK + r]) : 0;
    }
    __syncthreads();

    const uint32_t sb = smem_u32(sm);

    // A cp mapping: 2 thr/row, each handles 2 segs (32B) of both planes
    const int arow = tid >> 1, ah2 = (tid & 1) * 2;
    const __nv_bfloat16* aph = g_xhi + (size_t)toks[arow] * HDIM + ah2 * 8;
    const __nv_bfloat16* apl = g_xlo + (size_t)toks[arow] * HDIM + ah2 * 8;
    const uint32_t aD0 = sb + GU_AHI + SWZ64((uint32_t)(arow * 64 + (ah2 + 0) * 16));
    const uint32_t aD1 = sb + GU_AHI + SWZ64((uint32_t)(arow * 64 + (ah2 + 1) * 16));

    // B cp mapping: plane = tid>>6 (gh,gl,uh,ul), row = tid&63, 4 segs
    const int bpl = tid >> 6, brow = tid & 63;
    const __nv_bfloat16* bsrc;
    {
        const size_t bOff = ((size_t)z * MDIM + n0 + brow) * HDIM;
        if (bpl == 0)      bsrc = g_wghi + bOff;
        else if (bpl == 1) bsrc = g_wglo + bOff;
        else if (bpl == 2) bsrc = g_wuhi + bOff;
        else               bsrc = g_wulo + bOff;
    }
    const uint32_t bBase = sb + GU_BGH + bpl * 4096;
    const uint32_t bD0 = bBase + SWZ64((uint32_t)(brow * 64 + 0));
    const uint32_t bD1 = bBase + SWZ64((uint32_t)(brow * 64 + 16));
    const uint32_t bD2 = bBase + SWZ64((uint32_t)(brow * 64 + 32));
    const uint32_t bD3 = bBase + SWZ64((uint32_t)(brow * 64 + 48));

#define GU_CP(c, so_) do { uint32_t o = (so_); size_t ko = (size_t)(c) * 32;          \
    cp16(aD0 + o, aph + ko);      cp16(aD1 + o, aph + ko + 8);                        \
    cp16(aD0 + 8192 + o, apl + ko); cp16(aD1 + 8192 + o, apl + ko + 8);               \
    cp16(bD0 + o, bsrc + ko);      cp16(bD1 + o, bsrc + ko + 8);                      \
    cp16(bD2 + o, bsrc + ko + 16); cp16(bD3 + o, bsrc + ko + 24); } while (0)

    // compute fragment bases (warp grid 2m x 4n; warp tile 64x16)
    const int wm = wid & 1, wn = wid >> 1;
    const int aR = wm * 64 + (lane & 15);
    const int aS = lane >> 4;
    const int aSw = (aR >> 1) & 3;
    const uint32_t aHi0 = sb + GU_AHI + aR * 64 + (((0 + aS) ^ aSw) * 16);
    const uint32_t aHi1 = sb + GU_AHI + aR * 64 + (((2 + aS) ^ aSw) * 16);
    const int bR = wn * 16 + (lane & 7);
    const int bS = (lane >> 3) & 1;
    const int bSw = (bR >> 1) & 3;
    const uint32_t bF0 = sb + GU_BGH + bR * 64 + (((0 + bS) ^ bSw) * 16);
    const uint32_t bF1 = sb + GU_BGH + bR * 64 + (((2 + bS) ^ bSw) * 16);

    float accg[4][2][4] = {}, accu[4][2][4] = {};

    const int NC = HDIM / 32;
    GU_CP(0, 0); CP_COMMIT();
    GU_CP(1, GU_STG); CP_COMMIT();

    int cslot = 0, islot = 2;
    for (int c = 0; c < NC; c++) {
        const uint32_t so = cslot * GU_STG;
        CP_WAIT1();
        __syncthreads();
        if (c + 2 < NC) GU_CP(c + 2, islot * GU_STG);
        CP_COMMIT();
#pragma unroll
        for (int ks = 0; ks < 2; ks++) {
            const uint32_t aB = (ks ? aHi1 : aHi0) + so;
            const uint32_t bB = (ks ? bF1 : bF0) + so;
            uint32_t ah[4][4], al[4][4];
#pragma unroll
            for (int i = 0; i < 4; i++) {
                LDSM4(ah[i], aB + i * 1024);
                LDSM4(al[i], aB + 8192 + i * 1024);
            }
            uint32_t bgh[2][2], bgl[2][2], buh[2][2], bul[2][2];
#pragma unroll
            for (int j = 0; j < 2; j++) {
                LDSM2(bgh[j], bB + j * 512);
                LDSM2(bgl[j], bB + 4096 + j * 512);
                LDSM2(buh[j], bB + 8192 + j * 512);
                LDSM2(bul[j], bB + 12288 + j * 512);
            }
#pragma unroll
            for (int i = 0; i < 4; i++)
#pragma unroll
                for (int j = 0; j < 2; j++) {
                    MMA(accg[i][j], ah[i], bgh[j]);
                    MMA(accg[i][j], ah[i], bgl[j]);
                    MMA(accg[i][j], al[i], bgh[j]);
                    MMA(accu[i][j], ah[i], buh[j]);
                    MMA(accu[i][j], ah[i], bul[j]);
                    MMA(accu[i][j], al[i], buh[j]);
                }
        }
        cslot = (cslot == 2) ? 0 : cslot + 1;
        islot = (islot == 2) ? 0 : islot + 1;
    }

    // epilogue: silu(g)*u -> bf16 planes
    const int mrow = wm * 64 + (lane >> 2);
    const int col0 = n0 + wn * 16 + (lane & 3) * 2;
#pragma unroll
    for (int i = 0; i < 4; i++)
#pragma unroll
        for (int j = 0; j < 2; j++) {
            int col = col0 + j * 8;
#pragma unroll
            for (int half = 0; half < 2; half++) {
                int r = row0 + mrow + i * 16 + half * 8;
                if (r < nrows) {
                    float gv0 = accg[i][j][half * 2],     uv0 = accu[i][j][half * 2];
                    float gv1 = accg[i][j][half * 2 + 1], uv1 = accu[i][j][half * 2 + 1];
                    float a0 = (gv0 / (1.f + __expf(-gv0))) * uv0;
                    float a1 = (gv1 / (1.f + __expf(-gv1))) * uv1;
                    uint32_t hi, lo;
                    split2(a0, a1, hi, lo);
                    size_t idx = ((size_t)z * NTOK + r) * MDIM + col;
                    *(uint32_t*)(g_ahi + idx) = hi;
                    *(uint32_t*)(g_alo + idx) = lo;
                }
            }
        }
#undef GU_CP
}

// =======================================================================
// down: y[tok] += w * (act @ Wd^T)  tile 128x128, K chunk 32, 3-stage
// =======================================================================
#define DN_STG  32768
#define DN_AHI  0
#define DN_ALO  8192
#define DN_BH   16384
#define DN_BL   24576
#define DN_TOK  (3 * DN_STG)
#define DN_WTS  (DN_TOK + 512)
#define DN_SM   (DN_WTS + 512)

__global__ __launch_bounds__(256, 2)
void down_mma(float* __restrict__ y) {
    extern __shared__ __align__(128) char sm[];
    const int z = blockIdx.z;
    const bool SH = (z == NEXP);
    const int nrows = SH ? NTOK : g_cnt[z];
    const int row0 = blockIdx.x * 128;
    if (row0 >= nrows) return;
    const int h0 = blockIdx.y * 128;

    const int tid = threadIdx.x, wid = tid >> 5, lane = tid & 31;
    int* toks = (int*)(sm + DN_TOK);
    float* wts = (float*)(sm + DN_WTS);
    if (tid < 128) {
        int r = row0 + tid;
        if (r < nrows) {
            toks[tid] = SH ? r : g_tok[z * NTOK + r];
            wts[tid]  = SH ? 1.f : g_wt[z * NTOK + r];
        } else { toks[tid] = 0; wts[tid] = 0.f; }
    }
    __syncthreads();

    const uint32_t sb = smem_u32(sm);

    // A cp mapping: 2 thr/row, 2 segs of both planes
    const int arow = tid >> 1, ah2 = (tid & 1) * 2;
    const __nv_bfloat16* aph = g_ahi + ((size_t)z * NTOK + row0 + arow) * MDIM + ah2 * 8;
    const __nv_bfloat16* apl = g_alo + ((size_t)z * NTOK + row0 + arow) * MDIM + ah2 * 8;
    const uint32_t aD0 = sb + DN_AHI + SWZ64((uint32_t)(arow * 64 + (ah2 + 0) * 16));
    const uint32_t aD1 = sb + DN_AHI + SWZ64((uint32_t)(arow * 64 + (ah2 + 1) * 16));

    // B cp mapping: plane = tid>>7 (hi,lo), row = tid&127, 4 segs
    const int bpl = tid >> 7, brow = tid & 127;
    const size_t bOff = ((size_t)z * HDIM + h0 + brow) * MDIM;
    const __nv_bfloat16* bsrc = (bpl == 0) ? (g_wdhi + bOff) : (g_wdlo + bOff);
    const uint32_t bBase = sb + (bpl == 0 ? DN_BH : DN_BL);
    const uint32_t bD0 = bBase + SWZ64((uint32_t)(brow * 64 + 0));
    const uint32_t bD1 = bBase + SWZ64((uint32_t)(brow * 64 + 16));
    const uint32_t bD2 = bBase + SWZ64((uint32_t)(brow * 64 + 32));
    const uint32_t bD3 = bBase + SWZ64((uint32_t)(brow * 64 + 48));

#define DN_CP(c, so_) do { uint32_t o = (so_); size_t ko = (size_t)(c) * 32;          \
    cp16(aD0 + o, aph + ko);        cp16(aD1 + o, aph + ko + 8);                      \
    cp16(aD0 + 8192 + o, apl + ko); cp16(aD1 + 8192 + o, apl + ko + 8);               \
    cp16(bD0 + o, bsrc + ko);      cp16(bD1 + o, bsrc + ko + 8);                      \
    cp16(bD2 + o, bsrc + ko + 16); cp16(bD3 + o, bsrc + ko + 24); } while (0)

    const int wm = wid & 1, wn = wid >> 1;   // warp tile 64x32
    const int aR = wm * 64 + (lane & 15);
    const int aS = lane >> 4;
    const int aSw = (aR >> 1) & 3;
    const uint32_t aHi0 = sb + DN_AHI + aR * 64 + (((0 + aS) ^ aSw) * 16);
    const uint32_t aHi1 = sb + DN_AHI + aR * 64 + (((2 + aS) ^ aSw) * 16);
    const int bR = wn * 32 + (lane & 7);
    const int bS = (lane >> 3) & 1;
    const int bSw = (bR >> 1) & 3;
    const uint32_t bF0 = sb + DN_BH + bR * 64 + (((0 + bS) ^ bSw) * 16);
    const uint32_t bF1 = sb + DN_BH + bR * 64 + (((2 + bS) ^ bSw) * 16);

    float acc[4][4][4] = {};

    const int NC = MDIM / 32;
    DN_CP(0, 0); CP_COMMIT();
    DN_CP(1, DN_STG); CP_COMMIT();

    int cslot = 0, islot = 2;
    for (int c = 0; c < NC; c++) {
        const uint32_t so = cslot * DN_STG;
        CP_WAIT1();
        __syncthreads();
        if (c + 2 < NC) DN_CP(c + 2, islot * DN_STG);
        CP_COMMIT();
#pragma unroll
        for (int ks = 0; ks < 2; ks++) {
            const uint32_t aB = (ks ? aHi1 : aHi0) + so;
            const uint32_t bB = (ks ? bF1 : bF0) + so;
            uint32_t ah[4][4], al[4][4];
#pragma unroll
            for (int i = 0; i < 4; i++) {
                LDSM4(ah[i], aB + i * 1024);
                LDSM4(al[i], aB + 8192 + i * 1024);
            }
            uint32_t bh[4][2], bl[4][2];
#pragma unroll
            for (int j = 0; j < 4; j++) {
                LDSM2(bh[j], bB + j * 512);
                LDSM2(bl[j], bB + 8192 + j * 512);
            }
#pragma unroll
            for (int i = 0; i < 4; i++)
#pragma unroll
                for (int j = 0; j < 4; j++) {
                    MMA(acc[i][j], ah[i], bh[j]);
                    MMA(acc[i][j], ah[i], bl[j]);
                    MMA(acc[i][j], al[i], bh[j]);
                }
        }
        cslot = (cslot == 2) ? 0 : cslot + 1;
        islot = (islot == 2) ? 0 : islot + 1;
    }

    // epilogue: weighted atomic scatter
    const int mrow = wm * 64 + (lane >> 2);
    const int col0 = h0 + wn * 32 + (lane & 3) * 2;
#pragma unroll
    for (int i = 0; i < 4; i++)
#pragma unroll
        for (int half = 0; half < 2; half++) {
            int rl = mrow + i * 16 + half * 8;
            int r = row0 + rl;
            if (r < nrows) {
                float w = wts[rl];
                int tok = toks[rl];
                float* yp = y + (size_t)tok * HDIM;
#pragma unroll
                for (int j = 0; j < 4; j++) {
                    int col = col0 + j * 8;
                    atomicAdd(&yp[col],     acc[i][j][half * 2]     * w);
                    atomicAdd(&yp[col + 1], acc[i][j][half * 2 + 1] * w);
                }
            }
        }
#undef DN_CP
}

// ---------------- aux loss ----------------
__global__ void aux_kernel(float* __restrict__ p) {
    float a = 0.f;
#pragma unroll
    for (int e = 0; e < NEXP; e++) {
        float ce = (float)g_cnt[e] * ((float)NEXP / (float)(NTOK * 2));
        float pi = g_pisum[e] / (float)NTOK;
        a += ce * pi;
    }
    *p = a * 0.001f;
}

// ---------------- launch ----------------
extern "C" void kernel_launch(void* const* d_in, const int* in_sizes, int n_in,
                              void* d_out, int out_size) {
    (void)in_sizes; (void)n_in;
    const float* x   = (const float*)d_in[0];
    const float* gw  = (const float*)d_in[1];
    const float* wgt = (const float*)d_in[2];
    const float* wup = (const float*)d_in[3];
    const float* wdn = (const float*)d_in[4];
    const float* shg = (const float*)d_in[5];
    const float* shu = (const float*)d_in[6];
    const float* shd = (const float*)d_in[7];
    float* y = (float*)d_out;

    cudaFuncSetAttribute(gateup_mma, cudaFuncAttributeMaxDynamicSharedMemorySize, GU_SM);
    cudaFuncSetAttribute(down_mma,   cudaFuncAttributeMaxDynamicSharedMemorySize, DN_SM);

    zero_kernel<<<(NTOK * HDIM + 255) / 256, 256>>>(y);
    gate_kernel<<<NTOK, 256>>>(x, gw);
    xconv_kernel<<<(NTOK * HDIM + 255) / 256, 256>>>(x);

    const int NE4 = NEXP * MDIM * HDIM / 4;
    const int NS4 = MDIM * HDIM / 4;
    const size_t SOFF = (size_t)NEXP * MDIM * HDIM;
    wconv_kernel<<<(NE4 + 255) / 256, 256>>>((const float4*)wgt, 0, 0, NE4);
    wconv_kernel<<<(NE4 + 255) / 256, 256>>>((const float4*)wup, 1, 0, NE4);
    wconv_kernel<<<(NE4 + 255) / 256, 256>>>((const float4*)wdn, 2, 0, NE4);
    wconv_kernel<<<(NS4 + 255) / 256, 256>>>((const float4*)shg, 0, SOFF, NS4);
    wconv_kernel<<<(NS4 + 255) / 256, 256>>>((const float4*)shu, 1, SOFF, NS4);
    wconv_kernel<<<(NS4 + 255) / 256, 256>>>((const float4*)shd, 2, SOFF, NS4);

    gateup_mma<<<dim3(NTOK / 128, MDIM / 64, NEXP + 1), 256, GU_SM>>>();
    down_mma<<<dim3(NTOK / 128, HDIM / 128, NEXP + 1), 256, DN_SM>>>(y);

    if (out_size > NTOK * HDIM)
        aux_kernel<<<1, 1>>>(y + NTOK * HDIM);
}

// round 9
// speedup vs baseline: 1.0977x; 1.0977x over previous
#include <cuda_runtime.h>
#include <cuda_bf16.h>
#include <cstdint>

#define HDIM 2048
#define MDIM 1408
#define NEXP 8
#define NTOK 1024

// ---------------- device scratch ----------------
__device__ __nv_bfloat16 g_xhi[NTOK * HDIM];
__device__ __nv_bfloat16 g_xlo[NTOK * HDIM];
__device__ __nv_bfloat16 g_ahi[(NEXP + 1) * NTOK * MDIM];
__device__ __nv_bfloat16 g_alo[(NEXP + 1) * NTOK * MDIM];
// weight bf16 hi/lo planes; slot NEXP = shared expert
__device__ __nv_bfloat16 g_wghi[(NEXP + 1) * MDIM * HDIM];
__device__ __nv_bfloat16 g_wglo[(NEXP + 1) * MDIM * HDIM];
__device__ __nv_bfloat16 g_wuhi[(NEXP + 1) * MDIM * HDIM];
__device__ __nv_bfloat16 g_wulo[(NEXP + 1) * MDIM * HDIM];
__device__ __nv_bfloat16 g_wdhi[(NEXP + 1) * HDIM * MDIM];
__device__ __nv_bfloat16 g_wdlo[(NEXP + 1) * HDIM * MDIM];
__device__ int   g_tok[NEXP * NTOK];
__device__ float g_wt[NEXP * NTOK];
__device__ int   g_cnt[NEXP];
__device__ float g_pisum[NEXP];

// ---------------- helpers ----------------
__device__ __forceinline__ uint32_t smem_u32(const void* p) {
    uint32_t a;
    asm("{ .reg .u64 t; cvta.to.shared.u64 t, %1; cvt.u32.u64 %0, t; }" : "=r"(a) : "l"(p));
    return a;
}
__device__ __forceinline__ void cp16(uint32_t dst, const void* src) {
    asm volatile("cp.async.cg.shared.global [%0], [%1], 16;" :: "r"(dst), "l"(src));
}
#define CP_COMMIT() asm volatile("cp.async.commit_group;" ::: "memory")
#define CP_WAIT0()  asm volatile("cp.async.wait_group 0;" ::: "memory")

#define LDSM4(r, addr)                                                                       \
    asm volatile("ldmatrix.sync.aligned.m8n8.x4.shared.b16 {%0,%1,%2,%3}, [%4];"             \
                 : "=r"((r)[0]), "=r"((r)[1]), "=r"((r)[2]), "=r"((r)[3]) : "r"(addr))
#define LDSM2(r, addr)                                                                       \
    asm volatile("ldmatrix.sync.aligned.m8n8.x2.shared.b16 {%0,%1}, [%2];"                   \
                 : "=r"((r)[0]), "=r"((r)[1]) : "r"(addr))
#define MMA(c, a, b)                                                                         \
    asm volatile("mma.sync.aligned.m16n8k16.row.col.f32.bf16.bf16.f32 "                      \
                 "{%0,%1,%2,%3},{%4,%5,%6,%7},{%8,%9},{%0,%1,%2,%3};"                        \
                 : "+f"((c)[0]), "+f"((c)[1]), "+f"((c)[2]), "+f"((c)[3])                    \
                 : "r"((a)[0]), "r"((a)[1]), "r"((a)[2]), "r"((a)[3]), "r"((b)[0]), "r"((b)[1]))

__device__ __forceinline__ void split2(float a, float b, uint32_t& hi, uint32_t& lo) {
    __nv_bfloat16 ha = __float2bfloat16(a), hb = __float2bfloat16(b);
    float ra = a - __bfloat162float(ha), rb = b - __bfloat162float(hb);
    __nv_bfloat16 la = __float2bfloat16(ra), lb = __float2bfloat16(rb);
    __nv_bfloat162 hp; hp.x = ha; hp.y = hb;
    __nv_bfloat162 lp; lp.x = la; lp.y = lb;
    hi = *reinterpret_cast<uint32_t*>(&hp);
    lo = *reinterpret_cast<uint32_t*>(&lp);
}

#define LDS_ROW 80   // 32 bf16 + 16B pad -> conflict-free ldmatrix

// ---------------- init / conversions ----------------
// zero only y (placement-independent of gate)
__global__ void zeroy_kernel(float* __restrict__ y) {
    int i = blockIdx.x * blockDim.x + threadIdx.x;
    if (i < NTOK * HDIM) y[i] = 0.f;
}

// x -> bf16 planes; also resets routing counters (runs BEFORE gate)
__global__ void xconv_kernel(const float* __restrict__ x) {
    int i = blockIdx.x * blockDim.x + threadIdx.x;
    if (i < NTOK * HDIM) {
        float v = x[i];
        __nv_bfloat16 h = __float2bfloat16(v);
        __nv_bfloat16 l = __float2bfloat16(v - __bfloat162float(h));
        g_xhi[i] = h; g_xlo[i] = l;
    }
    if (i < NEXP) { g_cnt[i] = 0; g_pisum[i] = 0.f; }
}

// all 6 weight tensors -> bf16 hi/lo planes in ONE launch.
// blockIdx.y: 0=wg, 1=wu, 2=wd. Routed part [0, NE4) from routed tensor,
// shared part [NE4, NT4) from shared tensor. Destinations device-side.
__global__ __launch_bounds__(256)
void wconv_all(const float4* __restrict__ wg, const float4* __restrict__ wu,
               const float4* __restrict__ wd, const float4* __restrict__ sg,
               const float4* __restrict__ su, const float4* __restrict__ sd) {
    const int NE4 = NEXP * MDIM * HDIM / 4;
    const int NT4 = (NEXP + 1) * MDIM * HDIM / 4;
    int i = blockIdx.x * blockDim.x + threadIdx.x;
    if (i >= NT4) return;
    int which = blockIdx.y;
    __nv_bfloat16 *hb, *lb;
    const float4 *rsrc, *ssrc;
    if (which == 0)      { hb = g_wghi; lb = g_wglo; rsrc = wg; ssrc = sg; }
    else if (which == 1) { hb = g_wuhi; lb = g_wulo; rsrc = wu; ssrc = su; }
    else                 { hb = g_wdhi; lb = g_wdlo; rsrc = wd; ssrc = sd; }
    float4 v = (i < NE4) ? rsrc[i] : ssrc[i - NE4];
    uint2 h, l;
    split2(v.x, v.y, h.x, l.x);
    split2(v.z, v.w, h.y, l.y);
    ((uint2*)hb)[i] = h;
    ((uint2*)lb)[i] = l;
}

// ---------------- gate ----------------
__global__ __launch_bounds__(256)
void gate_kernel(const float* __restrict__ x, const float* __restrict__ gw) {
    const int t = blockIdx.x;
    const float* xr = x + (size_t)t * HDIM;
    float acc[NEXP];
#pragma unroll
    for (int e = 0; e < NEXP; e++) acc[e] = 0.f;
    for (int h = threadIdx.x; h < HDIM; h += 256) {
        float xv = xr[h];
#pragma unroll
        for (int e = 0; e < NEXP; e++) acc[e] = fmaf(xv, gw[e * HDIM + h], acc[e]);
    }
#pragma unroll
    for (int e = 0; e < NEXP; e++)
        for (int o = 16; o > 0; o >>= 1) acc[e] += __shfl_down_sync(0xffffffffu, acc[e], o);

    __shared__ float red[8][NEXP];
    int warp = threadIdx.x >> 5, lane = threadIdx.x & 31;
    if (lane == 0) {
#pragma unroll
        for (int e = 0; e < NEXP; e++) red[warp][e] = acc[e];
    }
    __syncthreads();
    if (threadIdx.x == 0) {
        float lg[NEXP];
#pragma unroll
        for (int e = 0; e < NEXP; e++) {
            float s = 0.f;
            for (int w = 0; w < 8; w++) s += red[w][e];
            lg[e] = s;
        }
        float mx = lg[0];
#pragma unroll
        for (int e = 1; e < NEXP; e++) mx = fmaxf(mx, lg[e]);
        float p[NEXP]; float den = 0.f;
#pragma unroll
        for (int e = 0; e < NEXP; e++) { p[e] = __expf(lg[e] - mx); den += p[e]; }
#pragma unroll
        for (int e = 0; e < NEXP; e++) p[e] /= den;
#pragma unroll
        for (int e = 0; e < NEXP; e++) atomicAdd(&g_pisum[e], p[e]);
        int i1 = 0;
#pragma unroll
        for (int e = 1; e < NEXP; e++) if (p[e] > p[i1]) i1 = e;
        int i2 = -1;
#pragma unroll
        for (int e = 0; e < NEXP; e++) {
            if (e == i1) continue;
            if (i2 < 0 || p[e] > p[i2]) i2 = e;
        }
        float w1 = p[i1], w2 = p[i2];
        float s2 = w1 + w2 + 1e-20f;
        w1 /= s2; w2 /= s2;
        int pos1 = atomicAdd(&g_cnt[i1], 1);
        g_tok[i1 * NTOK + pos1] = t; g_wt[i1 * NTOK + pos1] = w1;
        int pos2 = atomicAdd(&g_cnt[i2], 1);
        g_tok[i2 * NTOK + pos2] = t; g_wt[i2 * NTOK + pos2] = w2;
    }
}

// =======================================================================
// gateup: act = silu(X Wg^T) * (X Wu^T)   tile 128x64, K chunk 32, 2-stage
// grid z: 0..7 routed experts, 8 = shared expert   (R6 815us version)
// =======================================================================
#define STAGE  40960
#define GU_AHI 0
#define GU_ALO 10240
#define GU_BGH 20480
#define GU_BGL 25600
#define GU_BUH 30720
#define GU_BUL 35840
#define GU_TOK 81920
#define GU_SM  82432

__global__ __launch_bounds__(256, 2)
void gateup_mma() {
    extern __shared__ __align__(128) char sm[];
    const int z = blockIdx.z;
    const bool SH = (z == NEXP);
    const int nrows = SH ? NTOK : g_cnt[z];
    const int row0 = blockIdx.x * 128;
    if (row0 >= nrows) return;
    const int n0 = blockIdx.y * 64;

    const int tid = threadIdx.x, wid = tid >> 5, lane = tid & 31;
    int* toks = (int*)(sm + GU_TOK);
    if (tid < 128) {
        int r = row0 + tid;
        toks[tid] = (r < nrows) ? (SH ? r : g_tok[z * NTOK + r]) : 0;
    }
    __syncthreads();

    const uint32_t sb = smem_u32(sm);

    // A cp mapping: 2 thr/row (seg 16B), one cp16 per plane
    const int arow = tid >> 1, aseg = tid & 1;
    const __nv_bfloat16* aph = g_xhi + (size_t)toks[arow] * HDIM + aseg * 16;
    const __nv_bfloat16* apl = g_xlo + (size_t)toks[arow] * HDIM + aseg * 16;
    const uint32_t aDH = sb + GU_AHI + arow * LDS_ROW + aseg * 32;
    const uint32_t aDL = sb + GU_ALO + arow * LDS_ROW + aseg * 32;

    // B cp mapping: 4 thr/row, 16B per thread per plane (4 planes)
    const int brow = tid >> 2, bseg = tid & 3;
    const size_t bOff = ((size_t)z * MDIM + n0 + brow) * HDIM + bseg * 8;
    const __nv_bfloat16* pgh = g_wghi + bOff;
    const __nv_bfloat16* pgl = g_wglo + bOff;
    const __nv_bfloat16* puh = g_wuhi + bOff;
    const __nv_bfloat16* pul = g_wulo + bOff;
    const uint32_t bD = brow * LDS_ROW + bseg * 16;
    const uint32_t bDgh = sb + GU_BGH + bD, bDgl = sb + GU_BGL + bD;
    const uint32_t bDuh = sb + GU_BUH + bD, bDul = sb + GU_BUL + bD;

#define GU_CP(c, stg) do { uint32_t o = (stg) * STAGE; size_t ko = (size_t)(c) * 32;  \
    cp16(aDH + o,      aph + ko);      cp16(aDH + o + 16, aph + ko + 8);              \
    cp16(aDL + o,      apl + ko);      cp16(aDL + o + 16, apl + ko + 8);              \
    cp16(bDgh + o, pgh + ko);  cp16(bDgl + o, pgl + ko);                              \
    cp16(bDuh + o, puh + ko);  cp16(bDul + o, pul + ko); } while (0)

    // compute fragment bases (warp grid 2m x 4n; warp tile 64x16)
    const int wm = wid & 1, wn = wid >> 1;
    const uint32_t aOffL = (lane & 15) * LDS_ROW + (lane >> 4) * 16;
    const uint32_t bOffL = (lane & 7) * LDS_ROW + ((lane >> 3) & 1) * 16;
    const uint32_t aHiB = sb + GU_AHI + (wm * 64) * LDS_ROW + aOffL;
    const uint32_t aLoB = sb + GU_ALO + (wm * 64) * LDS_ROW + aOffL;
    const uint32_t bGH = sb + GU_BGH + (wn * 16) * LDS_ROW + bOffL;
    const uint32_t bGL = sb + GU_BGL + (wn * 16) * LDS_ROW + bOffL;
    const uint32_t bUH = sb + GU_BUH + (wn * 16) * LDS_ROW + bOffL;
    const uint32_t bUL = sb + GU_BUL + (wn * 16) * LDS_ROW + bOffL;

    float accg[4][2][4] = {}, accu[4][2][4] = {};

    GU_CP(0, 0); CP_COMMIT();

    const int NC = HDIM / 32;
    for (int c = 0; c < NC; c++) {
        const uint32_t so = (c & 1) * STAGE;
        CP_WAIT0();
        __syncthreads();
        if (c + 1 < NC) { GU_CP(c + 1, (c + 1) & 1); CP_COMMIT(); }
#pragma unroll
        for (int ks = 0; ks < 2; ks++) {
            uint32_t ah[4][4], al[4][4];
#pragma unroll
            for (int i = 0; i < 4; i++) {
                LDSM4(ah[i], aHiB + so + i * (16 * LDS_ROW) + ks * 32);
                LDSM4(al[i], aLoB + so + i * (16 * LDS_ROW) + ks * 32);
            }
            uint32_t bgh[2][2], bgl[2][2], buh[2][2], bul[2][2];
#pragma unroll
            for (int j = 0; j < 2; j++) {
                LDSM2(bgh[j], bGH + so + j * (8 * LDS_ROW) + ks * 32);
                LDSM2(bgl[j], bGL + so + j * (8 * LDS_ROW) + ks * 32);
                LDSM2(buh[j], bUH + so + j * (8 * LDS_ROW) + ks * 32);
                LDSM2(bul[j], bUL + so + j * (8 * LDS_ROW) + ks * 32);
            }
#pragma unroll
            for (int i = 0; i < 4; i++)
#pragma unroll
                for (int j = 0; j < 2; j++) {
                    MMA(accg[i][j], ah[i], bgh[j]);
                    MMA(accg[i][j], ah[i], bgl[j]);
                    MMA(accg[i][j], al[i], bgh[j]);
                    MMA(accu[i][j], ah[i], buh[j]);
                    MMA(accu[i][j], ah[i], bul[j]);
                    MMA(accu[i][j], al[i], buh[j]);
                }
        }
    }

    // epilogue: silu(g)*u -> bf16 planes
    const int mrow = wm * 64 + (lane >> 2);
    const int col0 = n0 + wn * 16 + (lane & 3) * 2;
#pragma unroll
    for (int i = 0; i < 4; i++)
#pragma unroll
        for (int j = 0; j < 2; j++) {
            int col = col0 + j * 8;
#pragma unroll
            for (int half = 0; half < 2; half++) {
                int r = row0 + mrow + i * 16 + half * 8;
                if (r < nrows) {
                    float gv0 = accg[i][j][half * 2],     uv0 = accu[i][j][half * 2];
                    float gv1 = accg[i][j][half * 2 + 1], uv1 = accu[i][j][half * 2 + 1];
                    float a0 = (gv0 / (1.f + __expf(-gv0))) * uv0;
                    float a1 = (gv1 / (1.f + __expf(-gv1))) * uv1;
                    uint32_t hi, lo;
                    split2(a0, a1, hi, lo);
                    size_t idx = ((size_t)z * NTOK + r) * MDIM + col;
                    *(uint32_t*)(g_ahi + idx) = hi;
                    *(uint32_t*)(g_alo + idx) = lo;
                }
            }
        }
#undef GU_CP
}

// =======================================================================
// down: y[tok] += w * (act @ Wd^T)   tile 128x128, K chunk 32, 2-stage
// =======================================================================
#define DN_AHI 0
#define DN_ALO 10240
#define DN_BH  20480
#define DN_BL  30720
#define DN_TOK 81920
#define DN_WTS 82432
#define DN_SM  82944

__global__ __launch_bounds__(256, 2)
void down_mma(float* __restrict__ y) {
    extern __shared__ __align__(128) char sm[];
    const int z = blockIdx.z;
    const bool SH = (z == NEXP);
    const int nrows = SH ? NTOK : g_cnt[z];
    const int row0 = blockIdx.x * 128;
    if (row0 >= nrows) return;
    const int h0 = blockIdx.y * 128;

    const int tid = threadIdx.x, wid = tid >> 5, lane = tid & 31;
    int* toks = (int*)(sm + DN_TOK);
    float* wts = (float*)(sm + DN_WTS);
    if (tid < 128) {
        int r = row0 + tid;
        if (r < nrows) {
            toks[tid] = SH ? r : g_tok[z * NTOK + r];
            wts[tid]  = SH ? 1.f : g_wt[z * NTOK + r];
        } else { toks[tid] = 0; wts[tid] = 0.f; }
    }
    __syncthreads();

    const uint32_t sb = smem_u32(sm);

    // A cp mapping: 2 thr/row, one cp16 per plane
    const int arow = tid >> 1, aseg = tid & 1;
    const __nv_bfloat16* aph = g_ahi + ((size_t)z * NTOK + row0 + arow) * MDIM + aseg * 16;
    const __nv_bfloat16* apl = g_alo + ((size_t)z * NTOK + row0 + arow) * MDIM + aseg * 16;
    const uint32_t aDH = sb + DN_AHI + arow * LDS_ROW + aseg * 32;
    const uint32_t aDL = sb + DN_ALO + arow * LDS_ROW + aseg * 32;

    // B cp mapping: 2 thr/row, 16B x2 per plane
    const size_t bOff = ((size_t)z * HDIM + h0 + arow) * MDIM + aseg * 16;
    const __nv_bfloat16* pbh = g_wdhi + bOff;
    const __nv_bfloat16* pbl = g_wdlo + bOff;
    const uint32_t bDH = sb + DN_BH + arow * LDS_ROW + aseg * 32;
    const uint32_t bDL = sb + DN_BL + arow * LDS_ROW + aseg * 32;

#define DN_CP(c, stg) do { uint32_t o = (stg) * STAGE; size_t ko = (size_t)(c) * 32;  \
    cp16(aDH + o,      aph + ko);      cp16(aDH + o + 16, aph + ko + 8);              \
    cp16(aDL + o,      apl + ko);      cp16(aDL + o + 16, apl + ko + 8);              \
    cp16(bDH + o,      pbh + ko);      cp16(bDH + o + 16, pbh + ko + 8);              \
    cp16(bDL + o,      pbl + ko);      cp16(bDL + o + 16, pbl + ko + 8); } while (0)

    const int wm = wid & 1, wn = wid >> 1;   // warp tile 64x32
    const uint32_t aOffL = (lane & 15) * LDS_ROW + (lane >> 4) * 16;
    const uint32_t bOffL = (lane & 7) * LDS_ROW + ((lane >> 3) & 1) * 16;
    const uint32_t aHiB = sb + DN_AHI + (wm * 64) * LDS_ROW + aOffL;
    const uint32_t aLoB = sb + DN_ALO + (wm * 64) * LDS_ROW + aOffL;
    const uint32_t bHB = sb + DN_BH + (wn * 32) * LDS_ROW + bOffL;
    const uint32_t bLB = sb + DN_BL + (wn * 32) * LDS_ROW + bOffL;

    float acc[4][4][4] = {};

    DN_CP(0, 0); CP_COMMIT();

    const int NC = MDIM / 32;
    for (int c = 0; c < NC; c++) {
        const uint32_t so = (c & 1) * STAGE;
        CP_WAIT0();
        __syncthreads();
        if (c + 1 < NC) { DN_CP(c + 1, (c + 1) & 1); CP_COMMIT(); }
#pragma unroll
        for (int ks = 0; ks < 2; ks++) {
            uint32_t ah[4][4], al[4][4];
#pragma unroll
            for (int i = 0; i < 4; i++) {
                LDSM4(ah[i], aHiB + so + i * (16 * LDS_ROW) + ks * 32);
                LDSM4(al[i], aLoB + so + i * (16 * LDS_ROW) + ks * 32);
            }
            uint32_t bh[4][2], bl[4][2];
#pragma unroll
            for (int j = 0; j < 4; j++) {
                LDSM2(bh[j], bHB + so + j * (8 * LDS_ROW) + ks * 32);
                LDSM2(bl[j], bLB + so + j * (8 * LDS_ROW) + ks * 32);
            }
#pragma unroll
            for (int i = 0; i < 4; i++)
#pragma unroll
                for (int j = 0; j < 4; j++) {
                    MMA(acc[i][j], ah[i], bh[j]);
                    MMA(acc[i][j], ah[i], bl[j]);
                    MMA(acc[i][j], al[i], bh[j]);
                }
        }
    }

    // epilogue: weighted atomic scatter
    const int mrow = wm * 64 + (lane >> 2);
    const int col0 = h0 + wn * 32 + (lane & 3) * 2;
#pragma unroll
    for (int i = 0; i < 4; i++)
#pragma unroll
        for (int half = 0; half < 2; half++) {
            int rl = mrow + i * 16 + half * 8;
            int r = row0 + rl;
            if (r < nrows) {
                float w = wts[rl];
                int tok = toks[rl];
                float* yp = y + (size_t)tok * HDIM;
#pragma unroll
                for (int j = 0; j < 4; j++) {
                    int col = col0 + j * 8;
                    atomicAdd(&yp[col],     acc[i][j][half * 2]     * w);
                    atomicAdd(&yp[col + 1], acc[i][j][half * 2 + 1] * w);
                }
            }
        }
#undef DN_CP
}

// ---------------- aux loss ----------------
__global__ void aux_kernel(float* __restrict__ p) {
    float a = 0.f;
#pragma unroll
    for (int e = 0; e < NEXP; e++) {
        float ce = (float)g_cnt[e] * ((float)NEXP / (float)(NTOK * 2));
        float pi = g_pisum[e] / (float)NTOK;
        a += ce * pi;
    }
    *p = a * 0.001f;
}

// ---------------- launch ----------------
extern "C" void kernel_launch(void* const* d_in, const int* in_sizes, int n_in,
                              void* d_out, int out_size) {
    (void)in_sizes; (void)n_in;
    const float* x   = (const float*)d_in[0];
    const float* gw  = (const float*)d_in[1];
    const float* wgt = (const float*)d_in[2];
    const float* wup = (const float*)d_in[3];
    const float* wdn = (const float*)d_in[4];
    const float* shg = (const float*)d_in[5];
    const float* shu = (const float*)d_in[6];
    const float* shd = (const float*)d_in[7];
    float* y = (float*)d_out;

    cudaFuncSetAttribute(gateup_mma, cudaFuncAttributeMaxDynamicSharedMemorySize, GU_SM);
    cudaFuncSetAttribute(down_mma,   cudaFuncAttributeMaxDynamicSharedMemorySize, DN_SM);

    // launch order places gateup_mma at index 3 (ncu capture slot)
    xconv_kernel<<<(NTOK * HDIM + 255) / 256, 256>>>(x);            // 0 (also resets cnt/pisum)
    const int NT4 = (NEXP + 1) * MDIM * HDIM / 4;
    wconv_all<<<dim3((NT4 + 255) / 256, 3), 256>>>(                 // 1
        (const float4*)wgt, (const float4*)wup, (const float4*)wdn,
        (const float4*)shg, (const float4*)shu, (const float4*)shd);
    gate_kernel<<<NTOK, 256>>>(x, gw);                              // 2
    gateup_mma<<<dim3(NTOK / 128, MDIM / 64, NEXP + 1), 256, GU_SM>>>();  // 3
    zeroy_kernel<<<(NTOK * HDIM + 255) / 256, 256>>>(y);            // 4
    down_mma<<<dim3(NTOK / 128, HDIM / 128, NEXP + 1), 256, DN_SM>>>(y);  // 5
    if (out_size > NTOK * HDIM)
        aux_kernel<<<1, 1>>>(y + NTOK * HDIM);                      // 6
}

// round 10
// speedup vs baseline: 1.4042x; 1.2792x over previous
#include <cuda_runtime.h>
#include <cuda_fp16.h>
#include <cstdint>

#define HDIM 2048
#define MDIM 1408
#define NEXP 8
#define NTOK 1024

// ---------------- device scratch ----------------
__device__ __half g_xhi[NTOK * HDIM];               // x fp16 hi
__device__ __half g_xlo[NTOK * HDIM];               // x fp16 lo (residual)
__device__ __half g_ahi[(NEXP + 1) * NTOK * MDIM];  // activations fp16 hi
__device__ __half g_alo[(NEXP + 1) * NTOK * MDIM];  // activations fp16 lo
// weights: SINGLE fp16 plane each; slot NEXP = shared expert
__device__ __half g_wgh[(NEXP + 1) * MDIM * HDIM];
__device__ __half g_wuh[(NEXP + 1) * MDIM * HDIM];
__device__ __half g_wdh[(NEXP + 1) * HDIM * MDIM];
__device__ int   g_tok[NEXP * NTOK];
__device__ float g_wt[NEXP * NTOK];
__device__ int   g_cnt[NEXP];
__device__ float g_pisum[NEXP];

// ---------------- helpers ----------------
__device__ __forceinline__ uint32_t smem_u32(const void* p) {
    uint32_t a;
    asm("{ .reg .u64 t; cvta.to.shared.u64 t, %1; cvt.u32.u64 %0, t; }" : "=r"(a) : "l"(p));
    return a;
}
__device__ __forceinline__ void cp16(uint32_t dst, const void* src) {
    asm volatile("cp.async.cg.shared.global [%0], [%1], 16;" :: "r"(dst), "l"(src));
}
#define CP_COMMIT() asm volatile("cp.async.commit_group;" ::: "memory")
#define CP_WAIT0()  asm volatile("cp.async.wait_group 0;" ::: "memory")

#define LDSM4(r, addr)                                                                       \
    asm volatile("ldmatrix.sync.aligned.m8n8.x4.shared.b16 {%0,%1,%2,%3}, [%4];"             \
                 : "=r"((r)[0]), "=r"((r)[1]), "=r"((r)[2]), "=r"((r)[3]) : "r"(addr))
#define LDSM2(r, addr)                                                                       \
    asm volatile("ldmatrix.sync.aligned.m8n8.x2.shared.b16 {%0,%1}, [%2];"                   \
                 : "=r"((r)[0]), "=r"((r)[1]) : "r"(addr))
#define MMA(c, a, b)                                                                         \
    asm volatile("mma.sync.aligned.m16n8k16.row.col.f32.f16.f16.f32 "                        \
                 "{%0,%1,%2,%3},{%4,%5,%6,%7},{%8,%9},{%0,%1,%2,%3};"                        \
                 : "+f"((c)[0]), "+f"((c)[1]), "+f"((c)[2]), "+f"((c)[3])                    \
                 : "r"((a)[0]), "r"((a)[1]), "r"((a)[2]), "r"((a)[3]), "r"((b)[0]), "r"((b)[1]))

// split two fp32 into fp16 hi pair + fp16 lo (residual) pair
__device__ __forceinline__ void hsplit2(float a, float b, uint32_t& hi, uint32_t& lo) {
    __half ha = __float2half(a), hb = __float2half(b);
    float ra = a - __half2float(ha), rb = b - __half2float(hb);
    __half2 hp = __halves2half2(ha, hb);
    __half2 lp = __halves2half2(__float2half(ra), __float2half(rb));
    hi = *reinterpret_cast<uint32_t*>(&hp);
    lo = *reinterpret_cast<uint32_t*>(&lp);
}
__device__ __forceinline__ uint32_t hpack2(float a, float b) {
    __half2 hp = __halves2half2(__float2half(a), __float2half(b));
    return *reinterpret_cast<uint32_t*>(&hp);
}

#define LDS_ROW 80   // 32 fp16 + 16B pad -> conflict-free ldmatrix

// ---------------- init / conversions ----------------
__global__ void zeroy_kernel(float* __restrict__ y) {
    int i = blockIdx.x * blockDim.x + threadIdx.x;
    if (i < NTOK * HDIM) y[i] = 0.f;
}

// x -> fp16 hi/lo planes; also resets routing counters (runs BEFORE gate)
__global__ void xconv_kernel(const float* __restrict__ x) {
    int i = blockIdx.x * blockDim.x + threadIdx.x;
    if (i < NTOK * HDIM) {
        float v = x[i];
        __half h = __float2half(v);
        g_xhi[i] = h;
        g_xlo[i] = __float2half(v - __half2float(h));
    }
    if (i < NEXP) { g_cnt[i] = 0; g_pisum[i] = 0.f; }
}

// all 6 weight tensors -> single fp16 plane each, ONE launch.
// blockIdx.y: 0=wg, 1=wu, 2=wd; [0,NE4) routed, [NE4,NT4) shared.
__global__ __launch_bounds__(256)
void wconv_all(const float4* __restrict__ wg, const float4* __restrict__ wu,
               const float4* __restrict__ wd, const float4* __restrict__ sg,
               const float4* __restrict__ su, const float4* __restrict__ sd) {
    const int NE4 = NEXP * MDIM * HDIM / 4;
    const int NT4 = (NEXP + 1) * MDIM * HDIM / 4;
    int i = blockIdx.x * blockDim.x + threadIdx.x;
    if (i >= NT4) return;
    int which = blockIdx.y;
    __half* hb;
    const float4 *rsrc, *ssrc;
    if (which == 0)      { hb = g_wgh; rsrc = wg; ssrc = sg; }
    else if (which == 1) { hb = g_wuh; rsrc = wu; ssrc = su; }
    else                 { hb = g_wdh; rsrc = wd; ssrc = sd; }
    float4 v = (i < NE4) ? rsrc[i] : ssrc[i - NE4];
    uint2 h;
    h.x = hpack2(v.x, v.y);
    h.y = hpack2(v.z, v.w);
    ((uint2*)hb)[i] = h;
}

// ---------------- gate ----------------
__global__ __launch_bounds__(256)
void gate_kernel(const float* __restrict__ x, const float* __restrict__ gw) {
    const int t = blockIdx.x;
    const float* xr = x + (size_t)t * HDIM;
    float acc[NEXP];
#pragma unroll
    for (int e = 0; e < NEXP; e++) acc[e] = 0.f;
    for (int h = threadIdx.x; h < HDIM; h += 256) {
        float xv = xr[h];
#pragma unroll
        for (int e = 0; e < NEXP; e++) acc[e] = fmaf(xv, gw[e * HDIM + h], acc[e]);
    }
#pragma unroll
    for (int e = 0; e < NEXP; e++)
        for (int o = 16; o > 0; o >>= 1) acc[e] += __shfl_down_sync(0xffffffffu, acc[e], o);

    __shared__ float red[8][NEXP];
    int warp = threadIdx.x >> 5, lane = threadIdx.x & 31;
    if (lane == 0) {
#pragma unroll
        for (int e = 0; e < NEXP; e++) red[warp][e] = acc[e];
    }
    __syncthreads();
    if (threadIdx.x == 0) {
        float lg[NEXP];
#pragma unroll
        for (int e = 0; e < NEXP; e++) {
            float s = 0.f;
            for (int w = 0; w < 8; w++) s += red[w][e];
            lg[e] = s;
        }
        float mx = lg[0];
#pragma unroll
        for (int e = 1; e < NEXP; e++) mx = fmaxf(mx, lg[e]);
        float p[NEXP]; float den = 0.f;
#pragma unroll
        for (int e = 0; e < NEXP; e++) { p[e] = __expf(lg[e] - mx); den += p[e]; }
#pragma unroll
        for (int e = 0; e < NEXP; e++) p[e] /= den;
#pragma unroll
        for (int e = 0; e < NEXP; e++) atomicAdd(&g_pisum[e], p[e]);
        int i1 = 0;
#pragma unroll
        for (int e = 1; e < NEXP; e++) if (p[e] > p[i1]) i1 = e;
        int i2 = -1;
#pragma unroll
        for (int e = 0; e < NEXP; e++) {
            if (e == i1) continue;
            if (i2 < 0 || p[e] > p[i2]) i2 = e;
        }
        float w1 = p[i1], w2 = p[i2];
        float s2 = w1 + w2 + 1e-20f;
        w1 /= s2; w2 /= s2;
        int pos1 = atomicAdd(&g_cnt[i1], 1);
        g_tok[i1 * NTOK + pos1] = t; g_wt[i1 * NTOK + pos1] = w1;
        int pos2 = atomicAdd(&g_cnt[i2], 1);
        g_tok[i2 * NTOK + pos2] = t; g_wt[i2 * NTOK + pos2] = w2;
    }
}

// =======================================================================
// gateup: act = silu(X Wg^T) * (X Wu^T)  tile 128x64, K chunk 32, 2-stage
// fp16 2-MMA scheme: D = ah*bh + al*bh. grid z: 0..7 routed, 8 = shared
// =======================================================================
#define STAGE  30720
#define GU_AHI 0
#define GU_ALO 10240
#define GU_BGH 20480
#define GU_BUH 25600
#define GU_TOK 61440
#define GU_SM  61952

__global__ __launch_bounds__(256, 2)
void gateup_mma() {
    extern __shared__ __align__(128) char sm[];
    const int z = blockIdx.z;
    const bool SH = (z == NEXP);
    const int nrows = SH ? NTOK : g_cnt[z];
    const int row0 = blockIdx.x * 128;
    if (row0 >= nrows) return;
    const int n0 = blockIdx.y * 64;

    const int tid = threadIdx.x, wid = tid >> 5, lane = tid & 31;
    int* toks = (int*)(sm + GU_TOK);
    if (tid < 128) {
        int r = row0 + tid;
        toks[tid] = (r < nrows) ? (SH ? r : g_tok[z * NTOK + r]) : 0;
    }
    __syncthreads();

    const uint32_t sb = smem_u32(sm);

    // A cp mapping: 2 thr/row, 32B (2 cp16) per plane
    const int arow = tid >> 1, aseg = tid & 1;
    const __half* aph = g_xhi + (size_t)toks[arow] * HDIM + aseg * 16;
    const __half* apl = g_xlo + (size_t)toks[arow] * HDIM + aseg * 16;
    const uint32_t aDH = sb + GU_AHI + arow * LDS_ROW + aseg * 32;
    const uint32_t aDL = sb + GU_ALO + arow * LDS_ROW + aseg * 32;

    // B cp mapping: 4 thr/row, 16B per thread per plane (2 planes)
    const int brow = tid >> 2, bseg = tid & 3;
    const size_t bOff = ((size_t)z * MDIM + n0 + brow) * HDIM + bseg * 8;
    const __half* pgh = g_wgh + bOff;
    const __half* puh = g_wuh + bOff;
    const uint32_t bD = brow * LDS_ROW + bseg * 16;
    const uint32_t bDgh = sb + GU_BGH + bD;
    const uint32_t bDuh = sb + GU_BUH + bD;

#define GU_CP(c, stg) do { uint32_t o = (stg) * STAGE; size_t ko = (size_t)(c) * 32;  \
    cp16(aDH + o,      aph + ko);      cp16(aDH + o + 16, aph + ko + 8);              \
    cp16(aDL + o,      apl + ko);      cp16(aDL + o + 16, apl + ko + 8);              \
    cp16(bDgh + o, pgh + ko);  cp16(bDuh + o, puh + ko); } while (0)

    // compute fragment bases (warp grid 2m x 4n; warp tile 64x16)
    const int wm = wid & 1, wn = wid >> 1;
    const uint32_t aOffL = (lane & 15) * LDS_ROW + (lane >> 4) * 16;
    const uint32_t bOffL = (lane & 7) * LDS_ROW + ((lane >> 3) & 1) * 16;
    const uint32_t aHiB = sb + GU_AHI + (wm * 64) * LDS_ROW + aOffL;
    const uint32_t aLoB = sb + GU_ALO + (wm * 64) * LDS_ROW + aOffL;
    const uint32_t bGH = sb + GU_BGH + (wn * 16) * LDS_ROW + bOffL;
    const uint32_t bUH = sb + GU_BUH + (wn * 16) * LDS_ROW + bOffL;

    float accg[4][2][4] = {}, accu[4][2][4] = {};

    GU_CP(0, 0); CP_COMMIT();

    const int NC = HDIM / 32;
    for (int c = 0; c < NC; c++) {
        const uint32_t so = (c & 1) * STAGE;
        CP_WAIT0();
        __syncthreads();
        if (c + 1 < NC) { GU_CP(c + 1, (c + 1) & 1); CP_COMMIT(); }
#pragma unroll
        for (int ks = 0; ks < 2; ks++) {
            uint32_t ah[4][4], al[4][4];
#pragma unroll
            for (int i = 0; i < 4; i++) {
                LDSM4(ah[i], aHiB + so + i * (16 * LDS_ROW) + ks * 32);
                LDSM4(al[i], aLoB + so + i * (16 * LDS_ROW) + ks * 32);
            }
            uint32_t bgh[2][2], buh[2][2];
#pragma unroll
            for (int j = 0; j < 2; j++) {
                LDSM2(bgh[j], bGH + so + j * (8 * LDS_ROW) + ks * 32);
                LDSM2(buh[j], bUH + so + j * (8 * LDS_ROW) + ks * 32);
            }
#pragma unroll
            for (int i = 0; i < 4; i++)
#pragma unroll
                for (int j = 0; j < 2; j++) {
                    MMA(accg[i][j], ah[i], bgh[j]);
                    MMA(accg[i][j], al[i], bgh[j]);
                    MMA(accu[i][j], ah[i], buh[j]);
                    MMA(accu[i][j], al[i], buh[j]);
                }
        }
    }

    // epilogue: silu(g)*u -> fp16 hi/lo planes
    const int mrow = wm * 64 + (lane >> 2);
    const int col0 = n0 + wn * 16 + (lane & 3) * 2;
#pragma unroll
    for (int i = 0; i < 4; i++)
#pragma unroll
        for (int j = 0; j < 2; j++) {
            int col = col0 + j * 8;
#pragma unroll
            for (int half = 0; half < 2; half++) {
                int r = row0 + mrow + i * 16 + half * 8;
                if (r < nrows) {
                    float gv0 = accg[i][j][half * 2],     uv0 = accu[i][j][half * 2];
                    float gv1 = accg[i][j][half * 2 + 1], uv1 = accu[i][j][half * 2 + 1];
                    float a0 = (gv0 / (1.f + __expf(-gv0))) * uv0;
                    float a1 = (gv1 / (1.f + __expf(-gv1))) * uv1;
                    uint32_t hi, lo;
                    hsplit2(a0, a1, hi, lo);
                    size_t idx = ((size_t)z * NTOK + r) * MDIM + col;
                    *(uint32_t*)(g_ahi + idx) = hi;
                    *(uint32_t*)(g_alo + idx) = lo;
                }
            }
        }
#undef GU_CP
}

// =======================================================================
// down: y[tok] += w * (act @ Wd^T)   tile 128x128, K chunk 32, 2-stage
// fp16 2-MMA scheme
// =======================================================================
#define DN_AHI 0
#define DN_ALO 10240
#define DN_BH  20480
#define DN_TOK 61440
#define DN_WTS 61952
#define DN_SM  62464

__global__ __launch_bounds__(256, 2)
void down_mma(float* __restrict__ y) {
    extern __shared__ __align__(128) char sm[];
    const int z = blockIdx.z;
    const bool SH = (z == NEXP);
    const int nrows = SH ? NTOK : g_cnt[z];
    const int row0 = blockIdx.x * 128;
    if (row0 >= nrows) return;
    const int h0 = blockIdx.y * 128;

    const int tid = threadIdx.x, wid = tid >> 5, lane = tid & 31;
    int* toks = (int*)(sm + DN_TOK);
    float* wts = (float*)(sm + DN_WTS);
    if (tid < 128) {
        int r = row0 + tid;
        if (r < nrows) {
            toks[tid] = SH ? r : g_tok[z * NTOK + r];
            wts[tid]  = SH ? 1.f : g_wt[z * NTOK + r];
        } else { toks[tid] = 0; wts[tid] = 0.f; }
    }
    __syncthreads();

    const uint32_t sb = smem_u32(sm);

    // A cp mapping: 2 thr/row, 2 cp16 per plane
    const int arow = tid >> 1, aseg = tid & 1;
    const __half* aph = g_ahi + ((size_t)z * NTOK + row0 + arow) * MDIM + aseg * 16;
    const __half* apl = g_alo + ((size_t)z * NTOK + row0 + arow) * MDIM + aseg * 16;
    const uint32_t aDH = sb + DN_AHI + arow * LDS_ROW + aseg * 32;
    const uint32_t aDL = sb + DN_ALO + arow * LDS_ROW + aseg * 32;

    // B cp mapping: 2 thr/row, single plane, 2 cp16
    const size_t bOff = ((size_t)z * HDIM + h0 + arow) * MDIM + aseg * 16;
    const __half* pbh = g_wdh + bOff;
    const uint32_t bDH = sb + DN_BH + arow * LDS_ROW + aseg * 32;

#define DN_CP(c, stg) do { uint32_t o = (stg) * STAGE; size_t ko = (size_t)(c) * 32;  \
    cp16(aDH + o,      aph + ko);      cp16(aDH + o + 16, aph + ko + 8);              \
    cp16(aDL + o,      apl + ko);      cp16(aDL + o + 16, apl + ko + 8);              \
    cp16(bDH + o,      pbh + ko);      cp16(bDH + o + 16, pbh + ko + 8); } while (0)

    const int wm = wid & 1, wn = wid >> 1;   // warp tile 64x32
    const uint32_t aOffL = (lane & 15) * LDS_ROW + (lane >> 4) * 16;
    const uint32_t bOffL = (lane & 7) * LDS_ROW + ((lane >> 3) & 1) * 16;
    const uint32_t aHiB = sb + DN_AHI + (wm * 64) * LDS_ROW + aOffL;
    const uint32_t aLoB = sb + DN_ALO + (wm * 64) * LDS_ROW + aOffL;
    const uint32_t bHB = sb + DN_BH + (wn * 32) * LDS_ROW + bOffL;

    float acc[4][4][4] = {};

    DN_CP(0, 0); CP_COMMIT();

    const int NC = MDIM / 32;
    for (int c = 0; c < NC; c++) {
        const uint32_t so = (c & 1) * STAGE;
        CP_WAIT0();
        __syncthreads();
        if (c + 1 < NC) { DN_CP(c + 1, (c + 1) & 1); CP_COMMIT(); }
#pragma unroll
        for (int ks = 0; ks < 2; ks++) {
            uint32_t ah[4][4], al[4][4];
#pragma unroll
            for (int i = 0; i < 4; i++) {
                LDSM4(ah[i], aHiB + so + i * (16 * LDS_ROW) + ks * 32);
                LDSM4(al[i], aLoB + so + i * (16 * LDS_ROW) + ks * 32);
            }
            uint32_t bh[4][2];
#pragma unroll
            for (int j = 0; j < 4; j++)
                LDSM2(bh[j], bHB + so + j * (8 * LDS_ROW) + ks * 32);
#pragma unroll
            for (int i = 0; i < 4; i++)
#pragma unroll
                for (int j = 0; j < 4; j++) {
                    MMA(acc[i][j], ah[i], bh[j]);
                    MMA(acc[i][j], al[i], bh[j]);
                }
        }
    }

    // epilogue: weighted atomic scatter
    const int mrow = wm * 64 + (lane >> 2);
    const int col0 = h0 + wn * 32 + (lane & 3) * 2;
#pragma unroll
    for (int i = 0; i < 4; i++)
#pragma unroll
        for (int half = 0; half < 2; half++) {
            int rl = mrow + i * 16 + half * 8;
            int r = row0 + rl;
            if (r < nrows) {
                float w = wts[rl];
                int tok = toks[rl];
                float* yp = y + (size_t)tok * HDIM;
#pragma unroll
                for (int j = 0; j < 4; j++) {
                    int col = col0 + j * 8;
                    atomicAdd(&yp[col],     acc[i][j][half * 2]     * w);
                    atomicAdd(&yp[col + 1], acc[i][j][half * 2 + 1] * w);
                }
            }
        }
#undef DN_CP
}

// ---------------- aux loss ----------------
__global__ void aux_kernel(float* __restrict__ p) {
    float a = 0.f;
#pragma unroll
    for (int e = 0; e < NEXP; e++) {
        float ce = (float)g_cnt[e] * ((float)NEXP / (float)(NTOK * 2));
        float pi = g_pisum[e] / (float)NTOK;
        a += ce * pi;
    }
    *p = a * 0.001f;
}

// ---------------- launch ----------------
extern "C" void kernel_launch(void* const* d_in, const int* in_sizes, int n_in,
                              void* d_out, int out_size) {
    (void)in_sizes; (void)n_in;
    const float* x   = (const float*)d_in[0];
    const float* gw  = (const float*)d_in[1];
    const float* wgt = (const float*)d_in[2];
    const float* wup = (const float*)d_in[3];
    const float* wdn = (const float*)d_in[4];
    const float* shg = (const float*)d_in[5];
    const float* shu = (const float*)d_in[6];
    const float* shd = (const float*)d_in[7];
    float* y = (float*)d_out;

    cudaFuncSetAttribute(gateup_mma, cudaFuncAttributeMaxDynamicSharedMemorySize, GU_SM);
    cudaFuncSetAttribute(down_mma,   cudaFuncAttributeMaxDynamicSharedMemorySize, DN_SM);

    // launch order keeps gateup_mma at index 3 (ncu capture slot)
    xconv_kernel<<<(NTOK * HDIM + 255) / 256, 256>>>(x);            // 0 (+ counter reset)
    const int NT4 = (NEXP + 1) * MDIM * HDIM / 4;
    wconv_all<<<dim3((NT4 + 255) / 256, 3), 256>>>(                 // 1
        (const float4*)wgt, (const float4*)wup, (const float4*)wdn,
        (const float4*)shg, (const float4*)shu, (const float4*)shd);
    gate_kernel<<<NTOK, 256>>>(x, gw);                              // 2
    gateup_mma<<<dim3(NTOK / 128, MDIM / 64, NEXP + 1), 256, GU_SM>>>();  // 3
    zeroy_kernel<<<(NTOK * HDIM + 255) / 256, 256>>>(y);            // 4
    down_mma<<<dim3(NTOK / 128, HDIM / 128, NEXP + 1), 256, DN_SM>>>(y);  // 5
    if (out_size > NTOK * HDIM)
        aux_kernel<<<1, 1>>>(y + NTOK * HDIM);                      // 6
}

// round 11
// speedup vs baseline: 1.5841x; 1.1281x over previous
#include <cuda_runtime.h>
#include <cuda_fp16.h>
#include <cstdint>

#define HDIM 2048
#define MDIM 1408
#define NEXP 8
#define NTOK 1024

// ---------------- device scratch ----------------
__device__ __half g_xhi[NTOK * HDIM];               // x fp16 hi
__device__ __half g_xlo[NTOK * HDIM];               // x fp16 lo (residual)
__device__ __half g_act[(NEXP + 1) * NTOK * MDIM];  // activations, single fp16 plane
// weights: SINGLE fp16 plane each; slot NEXP = shared expert
__device__ __half g_wgh[(NEXP + 1) * MDIM * HDIM];
__device__ __half g_wuh[(NEXP + 1) * MDIM * HDIM];
__device__ __half g_wdh[(NEXP + 1) * HDIM * MDIM];
__device__ int   g_tok[NEXP * NTOK];
__device__ float g_wt[NEXP * NTOK];
__device__ int   g_cnt[NEXP];
__device__ float g_pisum[NEXP];

// ---------------- helpers ----------------
__device__ __forceinline__ uint32_t smem_u32(const void* p) {
    uint32_t a;
    asm("{ .reg .u64 t; cvta.to.shared.u64 t, %1; cvt.u32.u64 %0, t; }" : "=r"(a) : "l"(p));
    return a;
}
__device__ __forceinline__ void cp16(uint32_t dst, const void* src) {
    asm volatile("cp.async.cg.shared.global [%0], [%1], 16;" :: "r"(dst), "l"(src));
}
#define CP_COMMIT() asm volatile("cp.async.commit_group;" ::: "memory")
#define CP_WAIT0()  asm volatile("cp.async.wait_group 0;" ::: "memory")

#define LDSM4(r, addr)                                                                       \
    asm volatile("ldmatrix.sync.aligned.m8n8.x4.shared.b16 {%0,%1,%2,%3}, [%4];"             \
                 : "=r"((r)[0]), "=r"((r)[1]), "=r"((r)[2]), "=r"((r)[3]) : "r"(addr))
#define LDSM2(r, addr)                                                                       \
    asm volatile("ldmatrix.sync.aligned.m8n8.x2.shared.b16 {%0,%1}, [%2];"                   \
                 : "=r"((r)[0]), "=r"((r)[1]) : "r"(addr))
#define MMA(c, a, b)                                                                         \
    asm volatile("mma.sync.aligned.m16n8k16.row.col.f32.f16.f16.f32 "                        \
                 "{%0,%1,%2,%3},{%4,%5,%6,%7},{%8,%9},{%0,%1,%2,%3};"                        \
                 : "+f"((c)[0]), "+f"((c)[1]), "+f"((c)[2]), "+f"((c)[3])                    \
                 : "r"((a)[0]), "r"((a)[1]), "r"((a)[2]), "r"((a)[3]), "r"((b)[0]), "r"((b)[1]))

__device__ __forceinline__ uint32_t hpack2(float a, float b) {
    __half2 hp = __halves2half2(__float2half(a), __float2half(b));
    return *reinterpret_cast<uint32_t*>(&hp);
}

#define LDS_ROW 80   // 32 fp16 + 16B pad -> conflict-free ldmatrix

// ---------------- init / conversions ----------------
__global__ void zeroy_kernel(float* __restrict__ y) {
    int i = blockIdx.x * blockDim.x + threadIdx.x;
    if (i < NTOK * HDIM) y[i] = 0.f;
}

// x -> fp16 hi/lo planes; also resets routing counters (runs BEFORE gate)
__global__ void xconv_kernel(const float* __restrict__ x) {
    int i = blockIdx.x * blockDim.x + threadIdx.x;
    if (i < NTOK * HDIM) {
        float v = x[i];
        __half h = __float2half(v);
        g_xhi[i] = h;
        g_xlo[i] = __float2half(v - __half2float(h));
    }
    if (i < NEXP) { g_cnt[i] = 0; g_pisum[i] = 0.f; }
}

// all 6 weight tensors -> single fp16 plane each, ONE launch.
__global__ __launch_bounds__(256)
void wconv_all(const float4* __restrict__ wg, const float4* __restrict__ wu,
               const float4* __restrict__ wd, const float4* __restrict__ sg,
               const float4* __restrict__ su, const float4* __restrict__ sd) {
    const int NE4 = NEXP * MDIM * HDIM / 4;
    const int NT4 = (NEXP + 1) * MDIM * HDIM / 4;
    int i = blockIdx.x * blockDim.x + threadIdx.x;
    if (i >= NT4) return;
    int which = blockIdx.y;
    __half* hb;
    const float4 *rsrc, *ssrc;
    if (which == 0)      { hb = g_wgh; rsrc = wg; ssrc = sg; }
    else if (which == 1) { hb = g_wuh; rsrc = wu; ssrc = su; }
    else                 { hb = g_wdh; rsrc = wd; ssrc = sd; }
    float4 v = (i < NE4) ? rsrc[i] : ssrc[i - NE4];
    uint2 h;
    h.x = hpack2(v.x, v.y);
    h.y = hpack2(v.z, v.w);
    ((uint2*)hb)[i] = h;
}

// ---------------- gate ----------------
__global__ __launch_bounds__(256)
void gate_kernel(const float* __restrict__ x, const float* __restrict__ gw) {
    const int t = blockIdx.x;
    const float* xr = x + (size_t)t * HDIM;
    float acc[NEXP];
#pragma unroll
    for (int e = 0; e < NEXP; e++) acc[e] = 0.f;
    for (int h = threadIdx.x; h < HDIM; h += 256) {
        float xv = xr[h];
#pragma unroll
        for (int e = 0; e < NEXP; e++) acc[e] = fmaf(xv, gw[e * HDIM + h], acc[e]);
    }
#pragma unroll
    for (int e = 0; e < NEXP; e++)
        for (int o = 16; o > 0; o >>= 1) acc[e] += __shfl_down_sync(0xffffffffu, acc[e], o);

    __shared__ float red[8][NEXP];
    int warp = threadIdx.x >> 5, lane = threadIdx.x & 31;
    if (lane == 0) {
#pragma unroll
        for (int e = 0; e < NEXP; e++) red[warp][e] = acc[e];
    }
    __syncthreads();
    if (threadIdx.x == 0) {
        float lg[NEXP];
#pragma unroll
        for (int e = 0; e < NEXP; e++) {
            float s = 0.f;
            for (int w = 0; w < 8; w++) s += red[w][e];
            lg[e] = s;
        }
        float mx = lg[0];
#pragma unroll
        for (int e = 1; e < NEXP; e++) mx = fmaxf(mx, lg[e]);
        float p[NEXP]; float den = 0.f;
#pragma unroll
        for (int e = 0; e < NEXP; e++) { p[e] = __expf(lg[e] - mx); den += p[e]; }
#pragma unroll
        for (int e = 0; e < NEXP; e++) p[e] /= den;
#pragma unroll
        for (int e = 0; e < NEXP; e++) atomicAdd(&g_pisum[e], p[e]);
        int i1 = 0;
#pragma unroll
        for (int e = 1; e < NEXP; e++) if (p[e] > p[i1]) i1 = e;
        int i2 = -1;
#pragma unroll
        for (int e = 0; e < NEXP; e++) {
            if (e == i1) continue;
            if (i2 < 0 || p[e] > p[i2]) i2 = e;
        }
        float w1 = p[i1], w2 = p[i2];
        float s2 = w1 + w2 + 1e-20f;
        w1 /= s2; w2 /= s2;
        int pos1 = atomicAdd(&g_cnt[i1], 1);
        g_tok[i1 * NTOK + pos1] = t; g_wt[i1 * NTOK + pos1] = w1;
        int pos2 = atomicAdd(&g_cnt[i2], 1);
        g_tok[i2 * NTOK + pos2] = t; g_wt[i2 * NTOK + pos2] = w2;
    }
}

// =======================================================================
// gateup: act = silu(X Wg^T) * (X Wu^T)  tile 128x64, K chunk 32, 2-stage
// fp16 2-MMA scheme (x hi+lo, weights single plane). z: 0..7 routed, 8=shared
// =======================================================================
#define GU_STAGE 30720
#define GU_AHI 0
#define GU_ALO 10240
#define GU_BGH 20480
#define GU_BUH 25600
#define GU_TOK 61440
#define GU_SM  61952

__global__ __launch_bounds__(256, 2)
void gateup_mma() {
    extern __shared__ __align__(128) char sm[];
    const int z = blockIdx.z;
    const bool SH = (z == NEXP);
    const int nrows = SH ? NTOK : g_cnt[z];
    const int row0 = blockIdx.x * 128;
    if (row0 >= nrows) return;
    const int n0 = blockIdx.y * 64;

    const int tid = threadIdx.x, wid = tid >> 5, lane = tid & 31;
    int* toks = (int*)(sm + GU_TOK);
    if (tid < 128) {
        int r = row0 + tid;
        toks[tid] = (r < nrows) ? (SH ? r : g_tok[z * NTOK + r]) : 0;
    }
    __syncthreads();

    const uint32_t sb = smem_u32(sm);

    const int arow = tid >> 1, aseg = tid & 1;
    const __half* aph = g_xhi + (size_t)toks[arow] * HDIM + aseg * 16;
    const __half* apl = g_xlo + (size_t)toks[arow] * HDIM + aseg * 16;
    const uint32_t aDH = sb + GU_AHI + arow * LDS_ROW + aseg * 32;
    const uint32_t aDL = sb + GU_ALO + arow * LDS_ROW + aseg * 32;

    const int brow = tid >> 2, bseg = tid & 3;
    const size_t bOff = ((size_t)z * MDIM + n0 + brow) * HDIM + bseg * 8;
    const __half* pgh = g_wgh + bOff;
    const __half* puh = g_wuh + bOff;
    const uint32_t bD = brow * LDS_ROW + bseg * 16;
    const uint32_t bDgh = sb + GU_BGH + bD;
    const uint32_t bDuh = sb + GU_BUH + bD;

#define GU_CP(c, stg) do { uint32_t o = (stg) * GU_STAGE; size_t ko = (size_t)(c) * 32; \
    cp16(aDH + o,      aph + ko);      cp16(aDH + o + 16, aph + ko + 8);                \
    cp16(aDL + o,      apl + ko);      cp16(aDL + o + 16, apl + ko + 8);                \
    cp16(bDgh + o, pgh + ko);  cp16(bDuh + o, puh + ko); } while (0)

    const int wm = wid & 1, wn = wid >> 1;
    const uint32_t aOffL = (lane & 15) * LDS_ROW + (lane >> 4) * 16;
    const uint32_t bOffL = (lane & 7) * LDS_ROW + ((lane >> 3) & 1) * 16;
    const uint32_t aHiB = sb + GU_AHI + (wm * 64) * LDS_ROW + aOffL;
    const uint32_t aLoB = sb + GU_ALO + (wm * 64) * LDS_ROW + aOffL;
    const uint32_t bGH = sb + GU_BGH + (wn * 16) * LDS_ROW + bOffL;
    const uint32_t bUH = sb + GU_BUH + (wn * 16) * LDS_ROW + bOffL;

    float accg[4][2][4] = {}, accu[4][2][4] = {};

    GU_CP(0, 0); CP_COMMIT();

    const int NC = HDIM / 32;
    for (int c = 0; c < NC; c++) {
        const uint32_t so = (c & 1) * GU_STAGE;
        CP_WAIT0();
        __syncthreads();
        if (c + 1 < NC) { GU_CP(c + 1, (c + 1) & 1); CP_COMMIT(); }
#pragma unroll
        for (int ks = 0; ks < 2; ks++) {
            uint32_t ah[4][4], al[4][4];
#pragma unroll
            for (int i = 0; i < 4; i++) {
                LDSM4(ah[i], aHiB + so + i * (16 * LDS_ROW) + ks * 32);
                LDSM4(al[i], aLoB + so + i * (16 * LDS_ROW) + ks * 32);
            }
            uint32_t bgh[2][2], buh[2][2];
#pragma unroll
            for (int j = 0; j < 2; j++) {
                LDSM2(bgh[j], bGH + so + j * (8 * LDS_ROW) + ks * 32);
                LDSM2(buh[j], bUH + so + j * (8 * LDS_ROW) + ks * 32);
            }
#pragma unroll
            for (int i = 0; i < 4; i++)
#pragma unroll
                for (int j = 0; j < 2; j++) {
                    MMA(accg[i][j], ah[i], bgh[j]);
                    MMA(accg[i][j], al[i], bgh[j]);
                    MMA(accu[i][j], ah[i], buh[j]);
                    MMA(accu[i][j], al[i], buh[j]);
                }
        }
    }

    // epilogue: silu(g)*u -> single fp16 plane
    const int mrow = wm * 64 + (lane >> 2);
    const int col0 = n0 + wn * 16 + (lane & 3) * 2;
#pragma unroll
    for (int i = 0; i < 4; i++)
#pragma unroll
        for (int j = 0; j < 2; j++) {
            int col = col0 + j * 8;
#pragma unroll
            for (int half = 0; half < 2; half++) {
                int r = row0 + mrow + i * 16 + half * 8;
                if (r < nrows) {
                    float gv0 = accg[i][j][half * 2],     uv0 = accu[i][j][half * 2];
                    float gv1 = accg[i][j][half * 2 + 1], uv1 = accu[i][j][half * 2 + 1];
                    float a0 = (gv0 / (1.f + __expf(-gv0))) * uv0;
                    float a1 = (gv1 / (1.f + __expf(-gv1))) * uv1;
                    size_t idx = ((size_t)z * NTOK + r) * MDIM + col;
                    *(uint32_t*)(g_act + idx) = hpack2(a0, a1);
                }
            }
        }
#undef GU_CP
}

// =======================================================================
// down: y[tok] += w * (act @ Wd^T)  tile 128x128, K chunk 32, 2-stage
// pure single-plane fp16: 1 MMA per product
// =======================================================================
#define DN_STAGE 20480
#define DN_A   0
#define DN_B   10240
#define DN_TOK 40960
#define DN_WTS 41472
#define DN_SM  41984

__global__ __launch_bounds__(256, 2)
void down_mma(float* __restrict__ y) {
    extern __shared__ __align__(128) char sm[];
    const int z = blockIdx.z;
    const bool SH = (z == NEXP);
    const int nrows = SH ? NTOK : g_cnt[z];
    const int row0 = blockIdx.x * 128;
    if (row0 >= nrows) return;
    const int h0 = blockIdx.y * 128;

    const int tid = threadIdx.x, wid = tid >> 5, lane = tid & 31;
    int* toks = (int*)(sm + DN_TOK);
    float* wts = (float*)(sm + DN_WTS);
    if (tid < 128) {
        int r = row0 + tid;
        if (r < nrows) {
            toks[tid] = SH ? r : g_tok[z * NTOK + r];
            wts[tid]  = SH ? 1.f : g_wt[z * NTOK + r];
        } else { toks[tid] = 0; wts[tid] = 0.f; }
    }
    __syncthreads();

    const uint32_t sb = smem_u32(sm);

    // A cp mapping: 2 thr/row, 2 cp16, single plane
    const int arow = tid >> 1, aseg = tid & 1;
    const __half* ap = g_act + ((size_t)z * NTOK + row0 + arow) * MDIM + aseg * 16;
    const uint32_t aD = sb + DN_A + arow * LDS_ROW + aseg * 32;

    // B cp mapping: 2 thr/row, 2 cp16, single plane
    const size_t bOff = ((size_t)z * HDIM + h0 + arow) * MDIM + aseg * 16;
    const __half* pb = g_wdh + bOff;
    const uint32_t bD = sb + DN_B + arow * LDS_ROW + aseg * 32;

#define DN_CP(c, stg) do { uint32_t o = (stg) * DN_STAGE; size_t ko = (size_t)(c) * 32; \
    cp16(aD + o,      ap + ko);      cp16(aD + o + 16, ap + ko + 8);                    \
    cp16(bD + o,      pb + ko);      cp16(bD + o + 16, pb + ko + 8); } while (0)

    const int wm = wid & 1, wn = wid >> 1;   // warp tile 64x32
    const uint32_t aOffL = (lane & 15) * LDS_ROW + (lane >> 4) * 16;
    const uint32_t bOffL = (lane & 7) * LDS_ROW + ((lane >> 3) & 1) * 16;
    const uint32_t aB = sb + DN_A + (wm * 64) * LDS_ROW + aOffL;
    const uint32_t bB = sb + DN_B + (wn * 32) * LDS_ROW + bOffL;

    float acc[4][4][4] = {};

    DN_CP(0, 0); CP_COMMIT();

    const int NC = MDIM / 32;
    for (int c = 0; c < NC; c++) {
        const uint32_t so = (c & 1) * DN_STAGE;
        CP_WAIT0();
        __syncthreads();
        if (c + 1 < NC) { DN_CP(c + 1, (c + 1) & 1); CP_COMMIT(); }
#pragma unroll
        for (int ks = 0; ks < 2; ks++) {
            uint32_t ah[4][4];
#pragma unroll
            for (int i = 0; i < 4; i++)
                LDSM4(ah[i], aB + so + i * (16 * LDS_ROW) + ks * 32);
            uint32_t bh[4][2];
#pragma unroll
            for (int j = 0; j < 4; j++)
                LDSM2(bh[j], bB + so + j * (8 * LDS_ROW) + ks * 32);
#pragma unroll
            for (int i = 0; i < 4; i++)
#pragma unroll
                for (int j = 0; j < 4; j++)
                    MMA(acc[i][j], ah[i], bh[j]);
        }
    }

    // epilogue: weighted atomic scatter
    const int mrow = wm * 64 + (lane >> 2);
    const int col0 = h0 + wn * 32 + (lane & 3) * 2;
#pragma unroll
    for (int i = 0; i < 4; i++)
#pragma unroll
        for (int half = 0; half < 2; half++) {
            int rl = mrow + i * 16 + half * 8;
            int r = row0 + rl;
            if (r < nrows) {
                float w = wts[rl];
                int tok = toks[rl];
                float* yp = y + (size_t)tok * HDIM;
#pragma unroll
                for (int j = 0; j < 4; j++) {
                    int col = col0 + j * 8;
                    atomicAdd(&yp[col],     acc[i][j][half * 2]     * w);
                    atomicAdd(&yp[col + 1], acc[i][j][half * 2 + 1] * w);
                }
            }
        }
#undef DN_CP
}

// ---------------- aux loss ----------------
__global__ void aux_kernel(float* __restrict__ p) {
    float a = 0.f;
#pragma unroll
    for (int e = 0; e < NEXP; e++) {
        float ce = (float)g_cnt[e] * ((float)NEXP / (float)(NTOK * 2));
        float pi = g_pisum[e] / (float)NTOK;
        a += ce * pi;
    }
    *p = a * 0.001f;
}

// ---------------- launch ----------------
extern "C" void kernel_launch(void* const* d_in, const int* in_sizes, int n_in,
                              void* d_out, int out_size) {
    (void)in_sizes; (void)n_in;
    const float* x   = (const float*)d_in[0];
    const float* gw  = (const float*)d_in[1];
    const float* wgt = (const float*)d_in[2];
    const float* wup = (const float*)d_in[3];
    const float* wdn = (const float*)d_in[4];
    const float* shg = (const float*)d_in[5];
    const float* shu = (const float*)d_in[6];
    const float* shd = (const float*)d_in[7];
    float* y = (float*)d_out;

    cudaFuncSetAttribute(gateup_mma, cudaFuncAttributeMaxDynamicSharedMemorySize, GU_SM);
    cudaFuncSetAttribute(down_mma,   cudaFuncAttributeMaxDynamicSharedMemorySize, DN_SM);

    // launch order keeps gateup_mma at index 3 (ncu capture slot)
    xconv_kernel<<<(NTOK * HDIM + 255) / 256, 256>>>(x);            // 0 (+ counter reset)
    const int NT4 = (NEXP + 1) * MDIM * HDIM / 4;
    wconv_all<<<dim3((NT4 + 255) / 256, 3), 256>>>(                 // 1
        (const float4*)wgt, (const float4*)wup, (const float4*)wdn,
        (const float4*)shg, (const float4*)shu, (const float4*)shd);
    gate_kernel<<<NTOK, 256>>>(x, gw);                              // 2
    gateup_mma<<<dim3(NTOK / 128, MDIM / 64, NEXP + 1), 256, GU_SM>>>();  // 3
    zeroy_kernel<<<(NTOK * HDIM + 255) / 256, 256>>>(y);            // 4
    down_mma<<<dim3(NTOK / 128, HDIM / 128, NEXP + 1), 256, DN_SM>>>(y);  // 5
    if (out_size > NTOK * HDIM)
        aux_kernel<<<1, 1>>>(y + NTOK * HDIM);                      // 6
}

// round 12
// speedup vs baseline: 1.9150x; 1.2089x over previous
#include <cuda_runtime.h>
#include <cuda_fp16.h>
#include <cstdint>

#define HDIM 2048
#define MDIM 1408
#define NEXP 8
#define NTOK 1024

// ---------------- device scratch ----------------
__device__ __half g_xh[NTOK * HDIM];                // x, single fp16 plane
__device__ __half g_act[(NEXP + 1) * NTOK * MDIM];  // activations, single fp16 plane
// weights: single fp16 plane each; slot NEXP = shared expert
__device__ __half g_wgh[(NEXP + 1) * MDIM * HDIM];
__device__ __half g_wuh[(NEXP + 1) * MDIM * HDIM];
__device__ __half g_wdh[(NEXP + 1) * HDIM * MDIM];
__device__ int   g_tok[NEXP * NTOK];
__device__ float g_wt[NEXP * NTOK];
__device__ int   g_cnt[NEXP];
__device__ float g_pisum[NEXP];

// ---------------- helpers ----------------
__device__ __forceinline__ uint32_t smem_u32(const void* p) {
    uint32_t a;
    asm("{ .reg .u64 t; cvta.to.shared.u64 t, %1; cvt.u32.u64 %0, t; }" : "=r"(a) : "l"(p));
    return a;
}
__device__ __forceinline__ void cp16(uint32_t dst, const void* src) {
    asm volatile("cp.async.cg.shared.global [%0], [%1], 16;" :: "r"(dst), "l"(src));
}
#define CP_COMMIT() asm volatile("cp.async.commit_group;" ::: "memory")
#define CP_WAIT0()  asm volatile("cp.async.wait_group 0;" ::: "memory")

#define LDSM4(r, addr)                                                                       \
    asm volatile("ldmatrix.sync.aligned.m8n8.x4.shared.b16 {%0,%1,%2,%3}, [%4];"             \
                 : "=r"((r)[0]), "=r"((r)[1]), "=r"((r)[2]), "=r"((r)[3]) : "r"(addr))
#define LDSM2(r, addr)                                                                       \
    asm volatile("ldmatrix.sync.aligned.m8n8.x2.shared.b16 {%0,%1}, [%2];"                   \
                 : "=r"((r)[0]), "=r"((r)[1]) : "r"(addr))
#define MMA(c, a, b)                                                                         \
    asm volatile("mma.sync.aligned.m16n8k16.row.col.f32.f16.f16.f32 "                        \
                 "{%0,%1,%2,%3},{%4,%5,%6,%7},{%8,%9},{%0,%1,%2,%3};"                        \
                 : "+f"((c)[0]), "+f"((c)[1]), "+f"((c)[2]), "+f"((c)[3])                    \
                 : "r"((a)[0]), "r"((a)[1]), "r"((a)[2]), "r"((a)[3]), "r"((b)[0]), "r"((b)[1]))

__device__ __forceinline__ uint32_t hpack2(float a, float b) {
    __half2 hp = __halves2half2(__float2half(a), __float2half(b));
    return *reinterpret_cast<uint32_t*>(&hp);
}

#define LDS_ROW 80   // 32 fp16 + 16B pad -> conflict-free ldmatrix

// ---------------- init / conversions ----------------
__global__ void zeroy_kernel(float* __restrict__ y) {
    int i = blockIdx.x * blockDim.x + threadIdx.x;
    if (i < NTOK * HDIM) y[i] = 0.f;
}

// x -> fp16; also resets routing counters (runs BEFORE gate)
__global__ void xconv_kernel(const float* __restrict__ x) {
    int i = blockIdx.x * blockDim.x + threadIdx.x;
    if (i < NTOK * HDIM) g_xh[i] = __float2half(x[i]);
    if (i < NEXP) { g_cnt[i] = 0; g_pisum[i] = 0.f; }
}

// all 6 weight tensors -> single fp16 plane each, ONE launch.
__global__ __launch_bounds__(256)
void wconv_all(const float4* __restrict__ wg, const float4* __restrict__ wu,
               const float4* __restrict__ wd, const float4* __restrict__ sg,
               const float4* __restrict__ su, const float4* __restrict__ sd) {
    const int NE4 = NEXP * MDIM * HDIM / 4;
    const int NT4 = (NEXP + 1) * MDIM * HDIM / 4;
    int i = blockIdx.x * blockDim.x + threadIdx.x;
    if (i >= NT4) return;
    int which = blockIdx.y;
    __half* hb;
    const float4 *rsrc, *ssrc;
    if (which == 0)      { hb = g_wgh; rsrc = wg; ssrc = sg; }
    else if (which == 1) { hb = g_wuh; rsrc = wu; ssrc = su; }
    else                 { hb = g_wdh; rsrc = wd; ssrc = sd; }
    float4 v = (i < NE4) ? rsrc[i] : ssrc[i - NE4];
    uint2 h;
    h.x = hpack2(v.x, v.y);
    h.y = hpack2(v.z, v.w);
    ((uint2*)hb)[i] = h;
}

// ---------------- gate ----------------
__global__ __launch_bounds__(256)
void gate_kernel(const float* __restrict__ x, const float* __restrict__ gw) {
    const int t = blockIdx.x;
    const float* xr = x + (size_t)t * HDIM;
    float acc[NEXP];
#pragma unroll
    for (int e = 0; e < NEXP; e++) acc[e] = 0.f;
    for (int h = threadIdx.x; h < HDIM; h += 256) {
        float xv = xr[h];
#pragma unroll
        for (int e = 0; e < NEXP; e++) acc[e] = fmaf(xv, gw[e * HDIM + h], acc[e]);
    }
#pragma unroll
    for (int e = 0; e < NEXP; e++)
        for (int o = 16; o > 0; o >>= 1) acc[e] += __shfl_down_sync(0xffffffffu, acc[e], o);

    __shared__ float red[8][NEXP];
    int warp = threadIdx.x >> 5, lane = threadIdx.x & 31;
    if (lane == 0) {
#pragma unroll
        for (int e = 0; e < NEXP; e++) red[warp][e] = acc[e];
    }
    __syncthreads();
    if (threadIdx.x == 0) {
        float lg[NEXP];
#pragma unroll
        for (int e = 0; e < NEXP; e++) {
            float s = 0.f;
            for (int w = 0; w < 8; w++) s += red[w][e];
            lg[e] = s;
        }
        float mx = lg[0];
#pragma unroll
        for (int e = 1; e < NEXP; e++) mx = fmaxf(mx, lg[e]);
        float p[NEXP]; float den = 0.f;
#pragma unroll
        for (int e = 0; e < NEXP; e++) { p[e] = __expf(lg[e] - mx); den += p[e]; }
#pragma unroll
        for (int e = 0; e < NEXP; e++) p[e] /= den;
#pragma unroll
        for (int e = 0; e < NEXP; e++) atomicAdd(&g_pisum[e], p[e]);
        int i1 = 0;
#pragma unroll
        for (int e = 1; e < NEXP; e++) if (p[e] > p[i1]) i1 = e;
        int i2 = -1;
#pragma unroll
        for (int e = 0; e < NEXP; e++) {
            if (e == i1) continue;
            if (i2 < 0 || p[e] > p[i2]) i2 = e;
        }
        float w1 = p[i1], w2 = p[i2];
        float s2 = w1 + w2 + 1e-20f;
        w1 /= s2; w2 /= s2;
        int pos1 = atomicAdd(&g_cnt[i1], 1);
        g_tok[i1 * NTOK + pos1] = t; g_wt[i1 * NTOK + pos1] = w1;
        int pos2 = atomicAdd(&g_cnt[i2], 1);
        g_tok[i2 * NTOK + pos2] = t; g_wt[i2 * NTOK + pos2] = w2;
    }
}

// =======================================================================
// gateup: act = silu(X Wg^T) * (X Wu^T)  tile 128x64, K chunk 32, 2-stage
// single-plane fp16: 1 MMA per product (g + u). z: 0..7 routed, 8=shared
// =======================================================================
#define GU_STAGE 20480
#define GU_A   0
#define GU_BGH 10240
#define GU_BUH 15360
#define GU_TOK 40960
#define GU_SM  41472

__global__ __launch_bounds__(256, 2)
void gateup_mma() {
    extern __shared__ __align__(128) char sm[];
    const int z = blockIdx.z;
    const bool SH = (z == NEXP);
    const int nrows = SH ? NTOK : g_cnt[z];
    const int row0 = blockIdx.x * 128;
    if (row0 >= nrows) return;
    const int n0 = blockIdx.y * 64;

    const int tid = threadIdx.x, wid = tid >> 5, lane = tid & 31;
    int* toks = (int*)(sm + GU_TOK);
    if (tid < 128) {
        int r = row0 + tid;
        toks[tid] = (r < nrows) ? (SH ? r : g_tok[z * NTOK + r]) : 0;
    }
    __syncthreads();

    const uint32_t sb = smem_u32(sm);

    // A cp mapping: 2 thr/row, 32B (2 cp16)
    const int arow = tid >> 1, aseg = tid & 1;
    const __half* ap = g_xh + (size_t)toks[arow] * HDIM + aseg * 16;
    const uint32_t aD = sb + GU_A + arow * LDS_ROW + aseg * 32;

    // B cp mapping: 4 thr/row, 16B per thread per plane (2 planes)
    const int brow = tid >> 2, bseg = tid & 3;
    const size_t bOff = ((size_t)z * MDIM + n0 + brow) * HDIM + bseg * 8;
    const __half* pgh = g_wgh + bOff;
    const __half* puh = g_wuh + bOff;
    const uint32_t bD = brow * LDS_ROW + bseg * 16;
    const uint32_t bDgh = sb + GU_BGH + bD;
    const uint32_t bDuh = sb + GU_BUH + bD;

#define GU_CP(c, stg) do { uint32_t o = (stg) * GU_STAGE; size_t ko = (size_t)(c) * 32; \
    cp16(aD + o,      ap + ko);      cp16(aD + o + 16, ap + ko + 8);                    \
    cp16(bDgh + o, pgh + ko);  cp16(bDuh + o, puh + ko); } while (0)

    // compute fragment bases (warp grid 2m x 4n; warp tile 64x16)
    const int wm = wid & 1, wn = wid >> 1;
    const uint32_t aOffL = (lane & 15) * LDS_ROW + (lane >> 4) * 16;
    const uint32_t bOffL = (lane & 7) * LDS_ROW + ((lane >> 3) & 1) * 16;
    const uint32_t aB = sb + GU_A + (wm * 64) * LDS_ROW + aOffL;
    const uint32_t bGH = sb + GU_BGH + (wn * 16) * LDS_ROW + bOffL;
    const uint32_t bUH = sb + GU_BUH + (wn * 16) * LDS_ROW + bOffL;

    float accg[4][2][4] = {}, accu[4][2][4] = {};

    GU_CP(0, 0); CP_COMMIT();

    const int NC = HDIM / 32;
    for (int c = 0; c < NC; c++) {
        const uint32_t so = (c & 1) * GU_STAGE;
        CP_WAIT0();
        __syncthreads();
        if (c + 1 < NC) { GU_CP(c + 1, (c + 1) & 1); CP_COMMIT(); }
#pragma unroll
        for (int ks = 0; ks < 2; ks++) {
            uint32_t ah[4][4];
#pragma unroll
            for (int i = 0; i < 4; i++)
                LDSM4(ah[i], aB + so + i * (16 * LDS_ROW) + ks * 32);
            uint32_t bgh[2][2], buh[2][2];
#pragma unroll
            for (int j = 0; j < 2; j++) {
                LDSM2(bgh[j], bGH + so + j * (8 * LDS_ROW) + ks * 32);
                LDSM2(buh[j], bUH + so + j * (8 * LDS_ROW) + ks * 32);
            }
#pragma unroll
            for (int i = 0; i < 4; i++)
#pragma unroll
                for (int j = 0; j < 2; j++) {
                    MMA(accg[i][j], ah[i], bgh[j]);
                    MMA(accu[i][j], ah[i], buh[j]);
                }
        }
    }

    // epilogue: silu(g)*u -> single fp16 plane
    const int mrow = wm * 64 + (lane >> 2);
    const int col0 = n0 + wn * 16 + (lane & 3) * 2;
#pragma unroll
    for (int i = 0; i < 4; i++)
#pragma unroll
        for (int j = 0; j < 2; j++) {
            int col = col0 + j * 8;
#pragma unroll
            for (int half = 0; half < 2; half++) {
                int r = row0 + mrow + i * 16 + half * 8;
                if (r < nrows) {
                    float gv0 = accg[i][j][half * 2],     uv0 = accu[i][j][half * 2];
                    float gv1 = accg[i][j][half * 2 + 1], uv1 = accu[i][j][half * 2 + 1];
                    float a0 = (gv0 / (1.f + __expf(-gv0))) * uv0;
                    float a1 = (gv1 / (1.f + __expf(-gv1))) * uv1;
                    size_t idx = ((size_t)z * NTOK + r) * MDIM + col;
                    *(uint32_t*)(g_act + idx) = hpack2(a0, a1);
                }
            }
        }
#undef GU_CP
}

// =======================================================================
// down: y[tok] += w * (act @ Wd^T)  tile 128x128, K chunk 32, 2-stage
// single-plane fp16: 1 MMA per product
// =======================================================================
#define DN_STAGE 20480
#define DN_A   0
#define DN_B   10240
#define DN_TOK 40960
#define DN_WTS 41472
#define DN_SM  41984

__global__ __launch_bounds__(256, 2)
void down_mma(float* __restrict__ y) {
    extern __shared__ __align__(128) char sm[];
    const int z = blockIdx.z;
    const bool SH = (z == NEXP);
    const int nrows = SH ? NTOK : g_cnt[z];
    const int row0 = blockIdx.x * 128;
    if (row0 >= nrows) return;
    const int h0 = blockIdx.y * 128;

    const int tid = threadIdx.x, wid = tid >> 5, lane = tid & 31;
    int* toks = (int*)(sm + DN_TOK);
    float* wts = (float*)(sm + DN_WTS);
    if (tid < 128) {
        int r = row0 + tid;
        if (r < nrows) {
            toks[tid] = SH ? r : g_tok[z * NTOK + r];
            wts[tid]  = SH ? 1.f : g_wt[z * NTOK + r];
        } else { toks[tid] = 0; wts[tid] = 0.f; }
    }
    __syncthreads();

    const uint32_t sb = smem_u32(sm);

    const int arow = tid >> 1, aseg = tid & 1;
    const __half* ap = g_act + ((size_t)z * NTOK + row0 + arow) * MDIM + aseg * 16;
    const uint32_t aD = sb + DN_A + arow * LDS_ROW + aseg * 32;

    const size_t bOff = ((size_t)z * HDIM + h0 + arow) * MDIM + aseg * 16;
    const __half* pb = g_wdh + bOff;
    const uint32_t bD = sb + DN_B + arow * LDS_ROW + aseg * 32;

#define DN_CP(c, stg) do { uint32_t o = (stg) * DN_STAGE; size_t ko = (size_t)(c) * 32; \
    cp16(aD + o,      ap + ko);      cp16(aD + o + 16, ap + ko + 8);                    \
    cp16(bD + o,      pb + ko);      cp16(bD + o + 16, pb + ko + 8); } while (0)

    const int wm = wid & 1, wn = wid >> 1;   // warp tile 64x32
    const uint32_t aOffL = (lane & 15) * LDS_ROW + (lane >> 4) * 16;
    const uint32_t bOffL = (lane & 7) * LDS_ROW + ((lane >> 3) & 1) * 16;
    const uint32_t aB = sb + DN_A + (wm * 64) * LDS_ROW + aOffL;
    const uint32_t bB = sb + DN_B + (wn * 32) * LDS_ROW + bOffL;

    float acc[4][4][4] = {};

    DN_CP(0, 0); CP_COMMIT();

    const int NC = MDIM / 32;
    for (int c = 0; c < NC; c++) {
        const uint32_t so = (c & 1) * DN_STAGE;
        CP_WAIT0();
        __syncthreads();
        if (c + 1 < NC) { DN_CP(c + 1, (c + 1) & 1); CP_COMMIT(); }
#pragma unroll
        for (int ks = 0; ks < 2; ks++) {
            uint32_t ah[4][4];
#pragma unroll
            for (int i = 0; i < 4; i++)
                LDSM4(ah[i], aB + so + i * (16 * LDS_ROW) + ks * 32);
            uint32_t bh[4][2];
#pragma unroll
            for (int j = 0; j < 4; j++)
                LDSM2(bh[j], bB + so + j * (8 * LDS_ROW) + ks * 32);
#pragma unroll
            for (int i = 0; i < 4; i++)
#pragma unroll
                for (int j = 0; j < 4; j++)
                    MMA(acc[i][j], ah[i], bh[j]);
        }
    }

    // epilogue: weighted atomic scatter
    const int mrow = wm * 64 + (lane >> 2);
    const int col0 = h0 + wn * 32 + (lane & 3) * 2;
#pragma unroll
    for (int i = 0; i < 4; i++)
#pragma unroll
        for (int half = 0; half < 2; half++) {
            int rl = mrow + i * 16 + half * 8;
            int r = row0 + rl;
            if (r < nrows) {
                float w = wts[rl];
                int tok = toks[rl];
                float* yp = y + (size_t)tok * HDIM;
#pragma unroll
                for (int j = 0; j < 4; j++) {
                    int col = col0 + j * 8;
                    atomicAdd(&yp[col],     acc[i][j][half * 2]     * w);
                    atomicAdd(&yp[col + 1], acc[i][j][half * 2 + 1] * w);
                }
            }
        }
#undef DN_CP
}

// ---------------- aux loss ----------------
__global__ void aux_kernel(float* __restrict__ p) {
    float a = 0.f;
#pragma unroll
    for (int e = 0; e < NEXP; e++) {
        float ce = (float)g_cnt[e] * ((float)NEXP / (float)(NTOK * 2));
        float pi = g_pisum[e] / (float)NTOK;
        a += ce * pi;
    }
    *p = a * 0.001f;
}

// ---------------- launch ----------------
extern "C" void kernel_launch(void* const* d_in, const int* in_sizes, int n_in,
                              void* d_out, int out_size) {
    (void)in_sizes; (void)n_in;
    const float* x   = (const float*)d_in[0];
    const float* gw  = (const float*)d_in[1];
    const float* wgt = (const float*)d_in[2];
    const float* wup = (const float*)d_in[3];
    const float* wdn = (const float*)d_in[4];
    const float* shg = (const float*)d_in[5];
    const float* shu = (const float*)d_in[6];
    const float* shd = (const float*)d_in[7];
    float* y = (float*)d_out;

    cudaFuncSetAttribute(gateup_mma, cudaFuncAttributeMaxDynamicSharedMemorySize, GU_SM);
    cudaFuncSetAttribute(down_mma,   cudaFuncAttributeMaxDynamicSharedMemorySize, DN_SM);

    // launch order keeps gateup_mma at index 3 (ncu capture slot)
    xconv_kernel<<<(NTOK * HDIM + 255) / 256, 256>>>(x);            // 0 (+ counter reset)
    const int NT4 = (NEXP + 1) * MDIM * HDIM / 4;
    wconv_all<<<dim3((NT4 + 255) / 256, 3), 256>>>(                 // 1
        (const float4*)wgt, (const float4*)wup, (const float4*)wdn,
        (const float4*)shg, (const float4*)shu, (const float4*)shd);
    gate_kernel<<<NTOK, 256>>>(x, gw);                              // 2
    gateup_mma<<<dim3(NTOK / 128, MDIM / 64, NEXP + 1), 256, GU_SM>>>();  // 3
    zeroy_kernel<<<(NTOK * HDIM + 255) / 256, 256>>>(y);            // 4
    down_mma<<<dim3(NTOK / 128, HDIM / 128, NEXP + 1), 256, DN_SM>>>(y);  // 5
    if (out_size > NTOK * HDIM)
        aux_kernel<<<1, 1>>>(y + NTOK * HDIM);                      // 6
}